// round 8
// baseline (speedup 1.0000x reference)
#include <cuda_runtime.h>
#include <cstdint>

// Problem constants
#define BB   2
#define SS   2048
#define DIM  2048
#define NH   16
#define KVH  4
#define HD   128
#define ROWS (BB*SS)          // 4096
#define QKVD 3072             // fused Q|K|V width
#define KOFF 2048
#define VOFF 2560

// ---------------------------------------------------------------------------
// Scratch (static device globals — no allocation)
// ---------------------------------------------------------------------------
__device__ float gXr [(size_t)ROWS * DIM];    // X, tf32, K-permuted (P8)
__device__ float gWt [(size_t)QKVD * DIM];    // [Wq|Wk|Wv]^T, tf32, P8
__device__ float gWot[(size_t)DIM * DIM];     // Wo^T, tf32, P8
__device__ float gQKV[(size_t)ROWS * QKVD];   // raw projections (no rope)
__device__ float gC  [(size_t)ROWS * DIM];    // attn ctx, tf32, P8

// ---------------------------------------------------------------------------
// helpers
// ---------------------------------------------------------------------------
__device__ __forceinline__ unsigned tf32u(float x) {
    unsigned u;
    asm("cvt.rna.tf32.f32 %0, %1;" : "=r"(u) : "f"(x));
    return u;
}
__device__ __forceinline__ float tf32f(float x) { return __uint_as_float(tf32u(x)); }
__device__ __forceinline__ float ex2(float x) {
    float r;
    asm("ex2.approx.ftz.f32 %0, %1;" : "=f"(r) : "f"(x));
    return r;
}

// P8 permute: within each 8-col group store {c0,c4,c1,c5,c2,c6,c3,c7}
__global__ void permute_round_x(const float* __restrict__ in,
                                float* __restrict__ out) {
    int idx = blockIdx.x * blockDim.x + threadIdx.x;   // one 8-group
    if (idx >= ROWS * (DIM / 8)) return;
    const float* s = in + (size_t)idx * 8;
    float4 v0 = *(const float4*)s;
    float4 v1 = *(const float4*)(s + 4);
    float* d = out + (size_t)idx * 8;
    *(float4*)d = make_float4(tf32f(v0.x), tf32f(v1.x), tf32f(v0.y), tf32f(v1.y));
    *(float4*)(d + 4) = make_float4(tf32f(v0.z), tf32f(v1.z), tf32f(v0.w), tf32f(v1.w));
}

// Transpose-pack all 4 weights: W[k][n] -> out[n][k P8-permuted], tf32.
// grid (64,64,4), block (32,8). z selects the weight.
__global__ void wpack_all(const float* __restrict__ wq,
                          const float* __restrict__ wk,
                          const float* __restrict__ wv,
                          const float* __restrict__ wo,
                          float* __restrict__ Wt, float* __restrict__ Wot) {
    const float* W;
    float* out;
    int Nw;
    int z = blockIdx.z;
    if (z == 0)      { W = wq; out = Wt;                         Nw = 2048; }
    else if (z == 1) { W = wo; out = Wot;                        Nw = 2048; }
    else if (z == 2) { W = wk; out = Wt + (size_t)2048 * 2048;   Nw = 512;  }
    else             { W = wv; out = Wt + (size_t)2560 * 2048;   Nw = 512;  }
    int n0 = blockIdx.x * 32;
    if (n0 >= Nw) return;

    __shared__ float t[32][33];
    int tx = threadIdx.x, ty = threadIdx.y;
    int k0 = blockIdx.y * 32;
    #pragma unroll
    for (int i = 0; i < 4; i++)
        t[ty + 8 * i][tx] = W[(size_t)(k0 + ty + 8 * i) * Nw + n0 + tx];
    __syncthreads();
    int grp = tx >> 3, pos = tx & 7;
    int ksrc = grp * 8 + ((pos >> 1) | ((pos & 1) << 2));   // P8
    #pragma unroll
    for (int i = 0; i < 4; i++)
        out[(size_t)(n0 + ty + 8 * i) * 2048 + k0 + tx] = tf32f(t[ksrc][ty + 8 * i]);
}

// ---------------------------------------------------------------------------
// TF32 GEMM v2 (R3, best measured): C[M,N] = A[M,K] @ Bt[N,K]^T, P8 layout.
// ---------------------------------------------------------------------------
#define GST 40
#define GEMM2_SMEM (2 * 2 * 128 * GST * 4)   // 81920 B

__device__ __forceinline__ void cp16(unsigned dst, const void* src) {
    asm volatile("cp.async.cg.shared.global [%0], [%1], 16;\n"
                 :: "r"(dst), "l"(src));
}

__device__ __forceinline__ void mma8(float* c, const unsigned* a,
                                     unsigned b0, unsigned b1) {
    asm volatile(
        "mma.sync.aligned.m16n8k8.row.col.f32.tf32.tf32.f32 "
        "{%0,%1,%2,%3}, {%4,%5,%6,%7}, {%8,%9}, {%0,%1,%2,%3};\n"
        : "+f"(c[0]), "+f"(c[1]), "+f"(c[2]), "+f"(c[3])
        : "r"(a[0]), "r"(a[1]), "r"(a[2]), "r"(a[3]), "r"(b0), "r"(b1));
}

__global__ __launch_bounds__(128) void tf32_gemm2(
    const float* __restrict__ A, const float* __restrict__ Bt,
    float* __restrict__ C, int N, int K)
{
    extern __shared__ float sm[];
    float* As = sm;                    // [2][128][GST]
    float* Bs = sm + 2 * 128 * GST;    // [2][128][GST]

    const int tid  = threadIdx.x;
    const int lane = tid & 31;
    const int w    = tid >> 5;
    const int g    = lane >> 2;
    const int l    = lane & 3;
    const int wm   = (w >> 1) * 64;
    const int wn   = (w & 1) * 64;
    const long bm  = (long)blockIdx.y * 128;
    const long bn  = (long)blockIdx.x * 128;

    const unsigned sAu = (unsigned)__cvta_generic_to_shared(As);
    const unsigned sBu = (unsigned)__cvta_generic_to_shared(Bs);

    const int frow = tid >> 3;
    const int fcol = (tid & 7) << 2;
    const float* Abase = A  + (bm + frow) * K + fcol;
    const float* Bbase = Bt + (bn + frow) * K + fcol;

    float acc[4][8][4];
    #pragma unroll
    for (int mt = 0; mt < 4; mt++)
        #pragma unroll
        for (int nt = 0; nt < 8; nt++)
            #pragma unroll
            for (int j = 0; j < 4; j++) acc[mt][nt][j] = 0.f;

    const int niter = K / 32;

    auto issue = [&](int it, int buf) {
        long k0 = (long)it * 32;
        #pragma unroll
        for (int p = 0; p < 8; p++)
            cp16(sAu + (unsigned)(((buf * 128 + frow + p * 16) * GST + fcol) * 4),
                 Abase + (long)p * 16 * K + k0);
        #pragma unroll
        for (int p = 0; p < 8; p++)
            cp16(sBu + (unsigned)(((buf * 128 + frow + p * 16) * GST + fcol) * 4),
                 Bbase + (long)p * 16 * K + k0);
        asm volatile("cp.async.commit_group;\n");
    };

    issue(0, 0);

    for (int it = 0; it < niter; it++) {
        const int buf = it & 1;
        if (it + 1 < niter) {
            issue(it + 1, buf ^ 1);
            asm volatile("cp.async.wait_group 1;\n");
        } else {
            asm volatile("cp.async.wait_group 0;\n");
        }
        __syncthreads();

        const float* Ab = As + buf * 128 * GST;
        const float* Bb = Bs + buf * 128 * GST;

        #pragma unroll
        for (int kk = 0; kk < 4; kk++) {
            float2 av[4][2];
            float2 bv[8];
            #pragma unroll
            for (int mt = 0; mt < 4; mt++) {
                av[mt][0] = *(const float2*)&Ab[(wm + mt * 16 + g)     * GST + kk * 8 + 2 * l];
                av[mt][1] = *(const float2*)&Ab[(wm + mt * 16 + g + 8) * GST + kk * 8 + 2 * l];
            }
            #pragma unroll
            for (int nt = 0; nt < 8; nt++)
                bv[nt] = *(const float2*)&Bb[(wn + nt * 8 + g) * GST + kk * 8 + 2 * l];

            #pragma unroll
            for (int mt = 0; mt < 4; mt++) {
                unsigned a[4];
                a[0] = __float_as_uint(av[mt][0].x);
                a[1] = __float_as_uint(av[mt][1].x);
                a[2] = __float_as_uint(av[mt][0].y);
                a[3] = __float_as_uint(av[mt][1].y);
                #pragma unroll
                for (int nt = 0; nt < 8; nt++)
                    mma8(acc[mt][nt], a,
                         __float_as_uint(bv[nt].x), __float_as_uint(bv[nt].y));
            }
        }
        __syncthreads();
    }

    #pragma unroll
    for (int mt = 0; mt < 4; mt++)
        #pragma unroll
        for (int nt = 0; nt < 8; nt++) {
            const float* c = acc[mt][nt];
            long row = bm + wm + mt * 16 + g;
            long col = bn + wn + nt * 8 + 2 * l;
            *(float2*)&C[row * N + col]       = make_float2(c[0], c[1]);
            *(float2*)&C[(row + 8) * N + col] = make_float2(c[2], c[3]);
        }
}

// ---------------------------------------------------------------------------
// Tensor-core flash attention with FUSED RoPE (applied during Q/K tile load).
// 64 q-rows, 4 warps, 64-key tiles. Q/K stored d-permuted (P8) in smem ->
// conflict-free LDS.64 fragments at stride 136. Ctx epilogue writes P8 layout.
// ---------------------------------------------------------------------------
#define KST 136
#define VST 136
#define PST 68
#define ATTN_SMEM ((64*KST + 64*VST + 64*PST) * 4)   // 87040 B

__global__ __launch_bounds__(128) void attn_mma(
    const float* __restrict__ QKVg,
    const float* __restrict__ cosT, const float* __restrict__ sinT,
    const float* __restrict__ alibi, const float* __restrict__ amask,
    float* __restrict__ Og)
{
    extern __shared__ float smn[];
    float* sK = smn;              // [64][136]
    float* sV = smn + 64 * KST;   // [64][136]
    float* sP = sV + 64 * VST;    // [64][68]
    float* sQ = smn;              // alias (temp, consumed before loop)

    const int tid  = threadIdx.x;
    const int lane = tid & 31;
    const int w    = tid >> 5;
    const int g    = lane >> 2;
    const int l    = lane & 3;
    const int bh   = blockIdx.y;
    const int b    = bh >> 4;
    const int h    = bh & 15;
    const int kvh  = h >> 2;
    const int bxr  = gridDim.x - 1 - blockIdx.x;   // heavy blocks first
    const int q0   = bxr * 64;
    const int ktiles = bxr + 1;

    // ---- load Q tile (64 x 128) with fused RoPE + P8 d-permute ----
    for (int i = tid; i < 64 * 8; i += 128) {
        int r = i >> 3, t = i & 7;          // row, 8-group in [0,64)
        int s = q0 + r;
        const float* src = &QKVg[(size_t)(b * SS + s) * QKVD + h * HD + 8 * t];
        const float* cs = cosT + s * HD + 8 * t;
        const float* sn = sinT + s * HD + 8 * t;
        float a[8], bb[8], c0v[8], s0v[8], c1v[8], s1v[8];
        *(float4*)(a)       = *(const float4*)(src);
        *(float4*)(a + 4)   = *(const float4*)(src + 4);
        *(float4*)(bb)      = *(const float4*)(src + 64);
        *(float4*)(bb + 4)  = *(const float4*)(src + 68);
        *(float4*)(c0v)     = *(const float4*)(cs);
        *(float4*)(c0v + 4) = *(const float4*)(cs + 4);
        *(float4*)(s0v)     = *(const float4*)(sn);
        *(float4*)(s0v + 4) = *(const float4*)(sn + 4);
        *(float4*)(c1v)     = *(const float4*)(cs + 64);
        *(float4*)(c1v + 4) = *(const float4*)(cs + 68);
        *(float4*)(s1v)     = *(const float4*)(sn + 64);
        *(float4*)(s1v + 4) = *(const float4*)(sn + 68);
        float oa[8], ob[8];
        #pragma unroll
        for (int j = 0; j < 8; j++) {
            oa[j] = a[j] * c0v[j] - bb[j] * s0v[j];
            ob[j] = bb[j] * c1v[j] + a[j] * s1v[j];
        }
        float wa[8], wb[8];
        #pragma unroll
        for (int j = 0; j < 4; j++) {
            wa[2 * j] = oa[j];  wa[2 * j + 1] = oa[j + 4];
            wb[2 * j] = ob[j];  wb[2 * j + 1] = ob[j + 4];
        }
        float* dq = &sQ[r * KST + 8 * t];
        *(float4*)(dq)      = *(float4*)(wa);
        *(float4*)(dq + 4)  = *(float4*)(wa + 4);
        *(float4*)(dq + 64) = *(float4*)(wb);
        *(float4*)(dq + 68) = *(float4*)(wb + 4);
    }
    __syncthreads();

    unsigned qf[16][4];
    #pragma unroll
    for (int kc = 0; kc < 16; kc++) {
        float2 q0v = *(const float2*)&sQ[(w * 16 + g)     * KST + kc * 8 + 2 * l];
        float2 q1v = *(const float2*)&sQ[(w * 16 + g + 8) * KST + kc * 8 + 2 * l];
        qf[kc][0] = tf32u(q0v.x);
        qf[kc][1] = tf32u(q1v.x);
        qf[kc][2] = tf32u(q0v.y);
        qf[kc][3] = tf32u(q1v.y);
    }
    __syncthreads();

    const float L2E = 1.4426950408889634f;
    const float SCL = 0.08838834764831845f * L2E;

    float m0 = -1e30f, m1 = -1e30f, s0 = 0.f, s1 = 0.f;
    float o[16][4];
    #pragma unroll
    for (int i = 0; i < 16; i++)
        #pragma unroll
        for (int j = 0; j < 4; j++) o[i][j] = 0.f;

    const int qrow = q0 + w * 16 + g;

    for (int kt = 0; kt < ktiles; kt++) {
        const int k0 = kt * 64;

        // ---- K tile: fused RoPE + P8 permute + tf32 round ----
        for (int i = tid; i < 64 * 8; i += 128) {
            int r = i >> 3, t = i & 7;
            int s = k0 + r;
            const float* src =
                &QKVg[(size_t)(b * SS + s) * QKVD + kvh * HD + KOFF + 8 * t];
            const float* cs = cosT + s * HD + 8 * t;
            const float* sn = sinT + s * HD + 8 * t;
            float a[8], bb[8], c0v[8], s0v[8], c1v[8], s1v[8];
            *(float4*)(a)       = *(const float4*)(src);
            *(float4*)(a + 4)   = *(const float4*)(src + 4);
            *(float4*)(bb)      = *(const float4*)(src + 64);
            *(float4*)(bb + 4)  = *(const float4*)(src + 68);
            *(float4*)(c0v)     = *(const float4*)(cs);
            *(float4*)(c0v + 4) = *(const float4*)(cs + 4);
            *(float4*)(s0v)     = *(const float4*)(sn);
            *(float4*)(s0v + 4) = *(const float4*)(sn + 4);
            *(float4*)(c1v)     = *(const float4*)(cs + 64);
            *(float4*)(c1v + 4) = *(const float4*)(cs + 68);
            *(float4*)(s1v)     = *(const float4*)(sn + 64);
            *(float4*)(s1v + 4) = *(const float4*)(sn + 68);
            float oa[8], ob[8];
            #pragma unroll
            for (int j = 0; j < 8; j++) {
                oa[j] = tf32f(a[j] * c0v[j] - bb[j] * s0v[j]);
                ob[j] = tf32f(bb[j] * c1v[j] + a[j] * s1v[j]);
            }
            float wa[8], wb[8];
            #pragma unroll
            for (int j = 0; j < 4; j++) {
                wa[2 * j] = oa[j];  wa[2 * j + 1] = oa[j + 4];
                wb[2 * j] = ob[j];  wb[2 * j + 1] = ob[j + 4];
            }
            float* dk = &sK[r * KST + 8 * t];
            *(float4*)(dk)      = *(float4*)(wa);
            *(float4*)(dk + 4)  = *(float4*)(wa + 4);
            *(float4*)(dk + 64) = *(float4*)(wb);
            *(float4*)(dk + 68) = *(float4*)(wb + 4);
        }
        // ---- V tile (normal layout, tf32 round) ----
        for (int i = tid; i < 64 * 32; i += 128) {
            int r = i >> 5, c4 = (i & 31) << 2;
            float4 vv = *(const float4*)
                &QKVg[(size_t)(b * SS + k0 + r) * QKVD + kvh * HD + VOFF + c4];
            vv.x = tf32f(vv.x); vv.y = tf32f(vv.y);
            vv.z = tf32f(vv.z); vv.w = tf32f(vv.w);
            *(float4*)&sV[r * VST + c4] = vv;
        }
        __syncthreads();

        // ---- QK^T ----
        float sc[8][4];
        #pragma unroll
        for (int nb = 0; nb < 8; nb++)
            #pragma unroll
            for (int j = 0; j < 4; j++) sc[nb][j] = 0.f;

        #pragma unroll
        for (int kc = 0; kc < 16; kc++) {
            #pragma unroll
            for (int nb = 0; nb < 8; nb++) {
                float2 kv2 = *(const float2*)&sK[(nb * 8 + g) * KST + kc * 8 + 2 * l];
                mma8(sc[nb], qf[kc],
                     __float_as_uint(kv2.x), __float_as_uint(kv2.y));
            }
        }

        // ---- scale + alibi + mask + causal (log2 domain) ----
        const bool diag = (k0 == q0);
        float mx0 = -1e30f, mx1 = -1e30f;
        {
            const float* alr = &alibi[((size_t)b * SS + qrow) * SS + k0 + 2 * l];
            const float* amr = &amask[b * SS + k0 + 2 * l];
            #pragma unroll
            for (int nb = 0; nb < 8; nb++) {
                float2 amv = *(const float2*)(amr + nb * 8);
                float2 al0 = *(const float2*)(alr + nb * 8);
                float2 al1 = *(const float2*)(alr + nb * 8 + 8 * SS);
                sc[nb][0] = sc[nb][0] * SCL + (al0.x + amv.x) * L2E;
                sc[nb][1] = sc[nb][1] * SCL + (al0.y + amv.y) * L2E;
                sc[nb][2] = sc[nb][2] * SCL + (al1.x + amv.x) * L2E;
                sc[nb][3] = sc[nb][3] * SCL + (al1.y + amv.y) * L2E;
                if (diag) {
                    int kc0 = k0 + nb * 8 + 2 * l;
                    if (kc0     > qrow)     sc[nb][0] = -1e9f;
                    if (kc0 + 1 > qrow)     sc[nb][1] = -1e9f;
                    if (kc0     > qrow + 8) sc[nb][2] = -1e9f;
                    if (kc0 + 1 > qrow + 8) sc[nb][3] = -1e9f;
                }
                mx0 = fmaxf(mx0, fmaxf(sc[nb][0], sc[nb][1]));
                mx1 = fmaxf(mx1, fmaxf(sc[nb][2], sc[nb][3]));
            }
        }

        mx0 = fmaxf(mx0, __shfl_xor_sync(0xffffffffu, mx0, 1));
        mx0 = fmaxf(mx0, __shfl_xor_sync(0xffffffffu, mx0, 2));
        mx1 = fmaxf(mx1, __shfl_xor_sync(0xffffffffu, mx1, 1));
        mx1 = fmaxf(mx1, __shfl_xor_sync(0xffffffffu, mx1, 2));

        float mn0 = fmaxf(m0, mx0), mn1 = fmaxf(m1, mx1);
        float c0 = ex2(m0 - mn0), c1 = ex2(m1 - mn1);
        m0 = mn0; m1 = mn1;

        float rs0 = 0.f, rs1 = 0.f;
        #pragma unroll
        for (int nb = 0; nb < 8; nb++) {
            float p00 = ex2(sc[nb][0] - m0);
            float p01 = ex2(sc[nb][1] - m0);
            float p10 = ex2(sc[nb][2] - m1);
            float p11 = ex2(sc[nb][3] - m1);
            rs0 += p00 + p01;
            rs1 += p10 + p11;
            *(float2*)&sP[(w * 16 + g)     * PST + nb * 8 + 2 * l] =
                make_float2(tf32f(p00), tf32f(p01));
            *(float2*)&sP[(w * 16 + g + 8) * PST + nb * 8 + 2 * l] =
                make_float2(tf32f(p10), tf32f(p11));
        }
        rs0 += __shfl_xor_sync(0xffffffffu, rs0, 1);
        rs0 += __shfl_xor_sync(0xffffffffu, rs0, 2);
        rs1 += __shfl_xor_sync(0xffffffffu, rs1, 1);
        rs1 += __shfl_xor_sync(0xffffffffu, rs1, 2);
        s0 = s0 * c0 + rs0;
        s1 = s1 * c1 + rs1;

        #pragma unroll
        for (int nb = 0; nb < 16; nb++) {
            o[nb][0] *= c0; o[nb][1] *= c0;
            o[nb][2] *= c1; o[nb][3] *= c1;
        }
        __syncwarp();

        // ---- O += P @ V ----
        #pragma unroll
        for (int kc = 0; kc < 8; kc++) {
            unsigned a[4];
            a[0] = __float_as_uint(sP[(w * 16 + g)     * PST + kc * 8 + l]);
            a[1] = __float_as_uint(sP[(w * 16 + g + 8) * PST + kc * 8 + l]);
            a[2] = __float_as_uint(sP[(w * 16 + g)     * PST + kc * 8 + l + 4]);
            a[3] = __float_as_uint(sP[(w * 16 + g + 8) * PST + kc * 8 + l + 4]);
            #pragma unroll
            for (int nb = 0; nb < 16; nb++) {
                unsigned b0 = __float_as_uint(sV[(kc * 8 + l)     * VST + nb * 8 + g]);
                unsigned b1 = __float_as_uint(sV[(kc * 8 + l + 4) * VST + nb * 8 + g]);
                mma8(o[nb], a, b0, b1);
            }
        }
        __syncthreads();
    }

    // ---- epilogue: O /= l, tf32-round, write P8-permuted ctx for Wo GEMM ----
    float inv0 = 1.0f / s0, inv1 = 1.0f / s1;
    size_t row0 = (size_t)(b * SS + qrow);
    const int pos0 = (l < 2) ? 4 * l : 4 * l - 7;
    #pragma unroll
    for (int nb = 0; nb < 16; nb++) {
        size_t cb = h * HD + nb * 8;
        Og[row0 * DIM + cb + pos0]           = tf32f(o[nb][0] * inv0);
        Og[row0 * DIM + cb + pos0 + 2]       = tf32f(o[nb][1] * inv0);
        Og[(row0 + 8) * DIM + cb + pos0]     = tf32f(o[nb][2] * inv1);
        Og[(row0 + 8) * DIM + cb + pos0 + 2] = tf32f(o[nb][3] * inv1);
    }
}

// ---------------------------------------------------------------------------
// Launch  (attn is the 4th launch -> profiled by ncu)
// ---------------------------------------------------------------------------
extern "C" void kernel_launch(void* const* d_in, const int* in_sizes, int n_in,
                              void* d_out, int out_size)
{
    const float* X     = (const float*)d_in[0];
    const float* cosT  = (const float*)d_in[1];
    const float* sinT  = (const float*)d_in[2];
    const float* alibi = (const float*)d_in[3];
    const float* amask = (const float*)d_in[4];
    const float* wq    = (const float*)d_in[5];
    const float* wk    = (const float*)d_in[6];
    const float* wv    = (const float*)d_in[7];
    const float* wo    = (const float*)d_in[8];
    float* out = (float*)d_out;

    float *Xr, *Wt, *Wot, *QKV, *C;
    cudaGetSymbolAddress((void**)&Xr,  gXr);
    cudaGetSymbolAddress((void**)&Wt,  gWt);
    cudaGetSymbolAddress((void**)&Wot, gWot);
    cudaGetSymbolAddress((void**)&QKV, gQKV);
    cudaGetSymbolAddress((void**)&C,   gC);

    cudaFuncSetAttribute(tf32_gemm2,
                         cudaFuncAttributeMaxDynamicSharedMemorySize, GEMM2_SMEM);
    cudaFuncSetAttribute(attn_mma,
                         cudaFuncAttributeMaxDynamicSharedMemorySize, ATTN_SMEM);

    // 1
    permute_round_x<<<ROWS * (DIM / 8) / 256, 256>>>(X, Xr);
    // 2
    wpack_all<<<dim3(64, 64, 4), dim3(32, 8)>>>(wq, wk, wv, wo, Wt, Wot);
    // 3: fused QKV projection (raw, rope applied in attention)
    tf32_gemm2<<<dim3(QKVD / 128, ROWS / 128), 128, GEMM2_SMEM>>>(
        Xr, Wt, QKV, QKVD, DIM);
    // 4: fused rope + flash attention  (profiled launch)
    attn_mma<<<dim3(SS / 64, BB * NH), 128, ATTN_SMEM>>>(
        QKV, cosT, sinT, alibi, amask, C);
    // 5: output projection
    tf32_gemm2<<<dim3(DIM / 128, ROWS / 128), 128, GEMM2_SMEM>>>(
        C, Wot, out, DIM, DIM);
}

// round 9
// speedup vs baseline: 1.2469x; 1.2469x over previous
#include <cuda_runtime.h>
#include <cstdint>

// Problem constants
#define BB   2
#define SS   2048
#define DIM  2048
#define NH   16
#define KVH  4
#define HD   128
#define ROWS (BB*SS)          // 4096
#define QKVD 3072             // fused Q|K|V width
#define KOFF 2048
#define VOFF 2560

// ---------------------------------------------------------------------------
// Scratch (static device globals — no allocation)
// ---------------------------------------------------------------------------
__device__ float gXr [(size_t)ROWS * DIM];    // X, tf32, K-permuted (P8)
__device__ float gWt [(size_t)QKVD * DIM];    // [Wq|Wk|Wv]^T, tf32, P8
__device__ float gWot[(size_t)DIM * DIM];     // Wo^T, tf32, P8
__device__ float gQKV[(size_t)ROWS * QKVD];   // tf32-rounded; Q,K roped+P8
__device__ float gC  [(size_t)ROWS * DIM];    // attn ctx, tf32, P8

// ---------------------------------------------------------------------------
// helpers
// ---------------------------------------------------------------------------
__device__ __forceinline__ unsigned tf32u(float x) {
    unsigned u;
    asm("cvt.rna.tf32.f32 %0, %1;" : "=r"(u) : "f"(x));
    return u;
}
__device__ __forceinline__ float tf32f(float x) { return __uint_as_float(tf32u(x)); }
__device__ __forceinline__ float ex2(float x) {
    float r;
    asm("ex2.approx.ftz.f32 %0, %1;" : "=f"(r) : "f"(x));
    return r;
}

// P8 permute: within each 8-col group store {c0,c4,c1,c5,c2,c6,c3,c7}
__global__ void permute_round_x(const float* __restrict__ in,
                                float* __restrict__ out) {
    int idx = blockIdx.x * blockDim.x + threadIdx.x;   // one 8-group
    if (idx >= ROWS * (DIM / 8)) return;
    const float* s = in + (size_t)idx * 8;
    float4 v0 = *(const float4*)s;
    float4 v1 = *(const float4*)(s + 4);
    float* d = out + (size_t)idx * 8;
    *(float4*)d = make_float4(tf32f(v0.x), tf32f(v1.x), tf32f(v0.y), tf32f(v1.y));
    *(float4*)(d + 4) = make_float4(tf32f(v0.z), tf32f(v1.z), tf32f(v0.w), tf32f(v1.w));
}

// Transpose-pack all 4 weights: W[k][n] -> out[n][k P8-permuted], tf32.
__global__ void wpack_all(const float* __restrict__ wq,
                          const float* __restrict__ wk,
                          const float* __restrict__ wv,
                          const float* __restrict__ wo,
                          float* __restrict__ Wt, float* __restrict__ Wot) {
    const float* W;
    float* out;
    int Nw;
    int z = blockIdx.z;
    if (z == 0)      { W = wq; out = Wt;                         Nw = 2048; }
    else if (z == 1) { W = wo; out = Wot;                        Nw = 2048; }
    else if (z == 2) { W = wk; out = Wt + (size_t)2048 * 2048;   Nw = 512;  }
    else             { W = wv; out = Wt + (size_t)2560 * 2048;   Nw = 512;  }
    int n0 = blockIdx.x * 32;
    if (n0 >= Nw) return;

    __shared__ float t[32][33];
    int tx = threadIdx.x, ty = threadIdx.y;
    int k0 = blockIdx.y * 32;
    #pragma unroll
    for (int i = 0; i < 4; i++)
        t[ty + 8 * i][tx] = W[(size_t)(k0 + ty + 8 * i) * Nw + n0 + tx];
    __syncthreads();
    int grp = tx >> 3, pos = tx & 7;
    int ksrc = grp * 8 + ((pos >> 1) | ((pos & 1) << 2));   // P8
    #pragma unroll
    for (int i = 0; i < 4; i++)
        out[(size_t)(n0 + ty + 8 * i) * 2048 + k0 + tx] = tf32f(t[ksrc][ty + 8 * i]);
}

// ---------------------------------------------------------------------------
// TF32 GEMM (R3 config): C[M,N] = A[M,K] @ Bt[N,K]^T, P8 layout.
// RND: round outputs to tf32 (used for the QKV projection).
// ---------------------------------------------------------------------------
#define GST 40
#define GEMM2_SMEM (2 * 2 * 128 * GST * 4)   // 81920 B

__device__ __forceinline__ void cp16(unsigned dst, const void* src) {
    asm volatile("cp.async.cg.shared.global [%0], [%1], 16;\n"
                 :: "r"(dst), "l"(src));
}

__device__ __forceinline__ void mma8(float* c, const unsigned* a,
                                     unsigned b0, unsigned b1) {
    asm volatile(
        "mma.sync.aligned.m16n8k8.row.col.f32.tf32.tf32.f32 "
        "{%0,%1,%2,%3}, {%4,%5,%6,%7}, {%8,%9}, {%0,%1,%2,%3};\n"
        : "+f"(c[0]), "+f"(c[1]), "+f"(c[2]), "+f"(c[3])
        : "r"(a[0]), "r"(a[1]), "r"(a[2]), "r"(a[3]), "r"(b0), "r"(b1));
}

template <bool RND>
__global__ __launch_bounds__(128) void tf32_gemm2(
    const float* __restrict__ A, const float* __restrict__ Bt,
    float* __restrict__ C, int N, int K)
{
    extern __shared__ float sm[];
    float* As = sm;                    // [2][128][GST]
    float* Bs = sm + 2 * 128 * GST;    // [2][128][GST]

    const int tid  = threadIdx.x;
    const int lane = tid & 31;
    const int w    = tid >> 5;
    const int g    = lane >> 2;
    const int l    = lane & 3;
    const int wm   = (w >> 1) * 64;
    const int wn   = (w & 1) * 64;
    const long bm  = (long)blockIdx.y * 128;
    const long bn  = (long)blockIdx.x * 128;

    const unsigned sAu = (unsigned)__cvta_generic_to_shared(As);
    const unsigned sBu = (unsigned)__cvta_generic_to_shared(Bs);

    const int frow = tid >> 3;
    const int fcol = (tid & 7) << 2;
    const float* Abase = A  + (bm + frow) * K + fcol;
    const float* Bbase = Bt + (bn + frow) * K + fcol;

    float acc[4][8][4];
    #pragma unroll
    for (int mt = 0; mt < 4; mt++)
        #pragma unroll
        for (int nt = 0; nt < 8; nt++)
            #pragma unroll
            for (int j = 0; j < 4; j++) acc[mt][nt][j] = 0.f;

    const int niter = K / 32;

    auto issue = [&](int it, int buf) {
        long k0 = (long)it * 32;
        #pragma unroll
        for (int p = 0; p < 8; p++)
            cp16(sAu + (unsigned)(((buf * 128 + frow + p * 16) * GST + fcol) * 4),
                 Abase + (long)p * 16 * K + k0);
        #pragma unroll
        for (int p = 0; p < 8; p++)
            cp16(sBu + (unsigned)(((buf * 128 + frow + p * 16) * GST + fcol) * 4),
                 Bbase + (long)p * 16 * K + k0);
        asm volatile("cp.async.commit_group;\n");
    };

    issue(0, 0);

    for (int it = 0; it < niter; it++) {
        const int buf = it & 1;
        if (it + 1 < niter) {
            issue(it + 1, buf ^ 1);
            asm volatile("cp.async.wait_group 1;\n");
        } else {
            asm volatile("cp.async.wait_group 0;\n");
        }
        __syncthreads();

        const float* Ab = As + buf * 128 * GST;
        const float* Bb = Bs + buf * 128 * GST;

        #pragma unroll
        for (int kk = 0; kk < 4; kk++) {
            float2 av[4][2];
            float2 bv[8];
            #pragma unroll
            for (int mt = 0; mt < 4; mt++) {
                av[mt][0] = *(const float2*)&Ab[(wm + mt * 16 + g)     * GST + kk * 8 + 2 * l];
                av[mt][1] = *(const float2*)&Ab[(wm + mt * 16 + g + 8) * GST + kk * 8 + 2 * l];
            }
            #pragma unroll
            for (int nt = 0; nt < 8; nt++)
                bv[nt] = *(const float2*)&Bb[(wn + nt * 8 + g) * GST + kk * 8 + 2 * l];

            #pragma unroll
            for (int mt = 0; mt < 4; mt++) {
                unsigned a[4];
                a[0] = __float_as_uint(av[mt][0].x);
                a[1] = __float_as_uint(av[mt][1].x);
                a[2] = __float_as_uint(av[mt][0].y);
                a[3] = __float_as_uint(av[mt][1].y);
                #pragma unroll
                for (int nt = 0; nt < 8; nt++)
                    mma8(acc[mt][nt], a,
                         __float_as_uint(bv[nt].x), __float_as_uint(bv[nt].y));
            }
        }
        __syncthreads();
    }

    #pragma unroll
    for (int mt = 0; mt < 4; mt++)
        #pragma unroll
        for (int nt = 0; nt < 8; nt++) {
            const float* c = acc[mt][nt];
            long row = bm + wm + mt * 16 + g;
            long col = bn + wn + nt * 8 + 2 * l;
            if (RND) {
                *(float2*)&C[row * N + col]       = make_float2(tf32f(c[0]), tf32f(c[1]));
                *(float2*)&C[(row + 8) * N + col] = make_float2(tf32f(c[2]), tf32f(c[3]));
            } else {
                *(float2*)&C[row * N + col]       = make_float2(c[0], c[1]);
                *(float2*)&C[(row + 8) * N + col] = make_float2(c[2], c[3]);
            }
        }
}

// ---------------------------------------------------------------------------
// RoPE in-place on Q/K, emitting d-PERMUTED 8-group layout {0,4,1,5,2,6,3,7},
// outputs tf32-rounded. Each thread owns whole logical groups (t, t+8).
// ---------------------------------------------------------------------------
__global__ void rope_kernel(float* __restrict__ x,
                            const float* __restrict__ cosT,
                            const float* __restrict__ sinT,
                            int nh_shift, int stride)
{
    int idx = blockIdx.x * blockDim.x + threadIdx.x;
    int nheads = 1 << nh_shift;
    int total = ROWS * nheads * 8;
    if (idx >= total) return;
    int t = idx & 7;
    int h = (idx >> 3) & (nheads - 1);
    int r = idx >> (3 + nh_shift);
    int s = r & (SS - 1);

    const float* cs = cosT + s * HD + 8 * t;
    const float* sn = sinT + s * HD + 8 * t;
    float* p = x + (size_t)r * stride + h * HD + 8 * t;

    float a[8], bv[8];
    *(float4*)(a)      = *(const float4*)(p);
    *(float4*)(a + 4)  = *(const float4*)(p + 4);
    *(float4*)(bv)     = *(const float4*)(p + 64);
    *(float4*)(bv + 4) = *(const float4*)(p + 68);

    float oa[8], ob[8];
    #pragma unroll
    for (int j = 0; j < 8; j++) {
        float c0 = cs[j],      s0 = sn[j];
        float c1 = cs[64 + j], s1 = sn[64 + j];
        oa[j] = tf32f(a[j] * c0 - bv[j] * s0);
        ob[j] = tf32f(bv[j] * c1 + a[j] * s1);
    }
    float wa[8], wb[8];
    #pragma unroll
    for (int j = 0; j < 4; j++) {
        wa[2 * j] = oa[j];  wa[2 * j + 1] = oa[j + 4];
        wb[2 * j] = ob[j];  wb[2 * j + 1] = ob[j + 4];
    }
    *(float4*)(p)      = *(float4*)(wa);
    *(float4*)(p + 4)  = *(float4*)(wa + 4);
    *(float4*)(p + 64) = *(float4*)(wb);
    *(float4*)(p + 68) = *(float4*)(wb + 4);
}

// ---------------------------------------------------------------------------
// cp.async-pipelined tensor-core flash attention.
// 64 q-rows, 4 warps, 64-key tiles. All tile data pre-rounded tf32 in gmem:
// raw cp.async copies, no cvt. V load overlaps QK^T; next K load overlaps
// softmax+PV. Q/K d-permuted (P8) -> conflict-free LDS.64 fragments.
// ---------------------------------------------------------------------------
#define KST 136
#define VST 136
#define PST 68
#define ATTN_SMEM ((64*KST + 64*VST + 64*PST) * 4)   // 87040 B

__global__ __launch_bounds__(128) void attn_mma(
    const float* __restrict__ QKVg,
    const float* __restrict__ alibi, const float* __restrict__ amask,
    float* __restrict__ Og)
{
    extern __shared__ float smn[];
    float* sK = smn;              // [64][136]
    float* sV = smn + 64 * KST;   // [64][136]  (also Q staging at start)
    float* sP = sV + 64 * VST;    // [64][68]

    const unsigned sKu = (unsigned)__cvta_generic_to_shared(sK);
    const unsigned sVu = (unsigned)__cvta_generic_to_shared(sV);

    const int tid  = threadIdx.x;
    const int lane = tid & 31;
    const int w    = tid >> 5;
    const int g    = lane >> 2;
    const int l    = lane & 3;
    const int bh   = blockIdx.y;
    const int b    = bh >> 4;
    const int h    = bh & 15;
    const int kvh  = h >> 2;
    const int bxr  = gridDim.x - 1 - blockIdx.x;   // heavy blocks first
    const int q0   = bxr * 64;
    const int ktiles = bxr + 1;

    // loader mapping: 16 x 16B chunks per thread per 64x128 tile
    const int lr = tid >> 1;            // rows lr, lr+... pattern via i
    (void)lr;

    auto load_tile = [&](unsigned dstu, int row0, int coloff) {
        #pragma unroll
        for (int it = 0; it < 16; it++) {
            int i = tid + it * 128;
            int r = i >> 5, c4 = (i & 31) << 2;
            cp16(dstu + (unsigned)((r * KST + c4) * 4),
                 &QKVg[(size_t)(b * SS + row0 + r) * QKVD + coloff + c4]);
        }
        asm volatile("cp.async.commit_group;\n" ::: "memory");
    };

    // stage Q into sV region; K[0] into sK
    load_tile(sVu, q0, h * HD);           // group: Q
    load_tile(sKu, q0 /*k0=0*/ - q0, kvh * HD + KOFF);  // K tile 0 at rows 0..63
    asm volatile("cp.async.wait_group 1;\n" ::: "memory");   // Q done
    __syncthreads();

    unsigned qf[16][4];
    #pragma unroll
    for (int kc = 0; kc < 16; kc++) {
        float2 q0v = *(const float2*)&sV[(w * 16 + g)     * VST + kc * 8 + 2 * l];
        float2 q1v = *(const float2*)&sV[(w * 16 + g + 8) * VST + kc * 8 + 2 * l];
        qf[kc][0] = __float_as_uint(q0v.x);
        qf[kc][1] = __float_as_uint(q1v.x);
        qf[kc][2] = __float_as_uint(q0v.y);
        qf[kc][3] = __float_as_uint(q1v.y);
    }
    __syncthreads();
    load_tile(sVu, 0, kvh * HD + VOFF);   // V[0]

    const float L2E = 1.4426950408889634f;
    const float SCL = 0.08838834764831845f * L2E;

    float m0 = -1e30f, m1 = -1e30f, s0 = 0.f, s1 = 0.f;
    float o[16][4];
    #pragma unroll
    for (int i = 0; i < 16; i++)
        #pragma unroll
        for (int j = 0; j < 4; j++) o[i][j] = 0.f;

    const int qrow = q0 + w * 16 + g;

    for (int kt = 0; kt < ktiles; kt++) {
        const int k0 = kt * 64;
        const bool has_next = (kt + 1 < ktiles);

        // K[kt] ready (V[kt] may still be in flight)
        asm volatile("cp.async.wait_group 1;\n" ::: "memory");
        __syncthreads();

        // ---- QK^T (overlaps in-flight V[kt]) ----
        float sc[8][4];
        #pragma unroll
        for (int nb = 0; nb < 8; nb++)
            #pragma unroll
            for (int j = 0; j < 4; j++) sc[nb][j] = 0.f;

        #pragma unroll
        for (int kc = 0; kc < 16; kc++) {
            #pragma unroll
            for (int nb = 0; nb < 8; nb++) {
                float2 kv2 = *(const float2*)&sK[(nb * 8 + g) * KST + kc * 8 + 2 * l];
                mma8(sc[nb], qf[kc],
                     __float_as_uint(kv2.x), __float_as_uint(kv2.y));
            }
        }
        __syncthreads();                      // all K reads done
        if (has_next)
            load_tile(sKu, k0 + 64, kvh * HD + KOFF);   // prefetch K[kt+1]

        // ---- scale + alibi + mask + causal (log2 domain) ----
        const bool diag = (k0 == q0);
        float mx0 = -1e30f, mx1 = -1e30f;
        {
            const float* alr = &alibi[((size_t)b * SS + qrow) * SS + k0 + 2 * l];
            const float* amr = &amask[b * SS + k0 + 2 * l];
            #pragma unroll
            for (int nb = 0; nb < 8; nb++) {
                float2 amv = *(const float2*)(amr + nb * 8);
                float2 al0 = *(const float2*)(alr + nb * 8);
                float2 al1 = *(const float2*)(alr + nb * 8 + 8 * SS);
                sc[nb][0] = sc[nb][0] * SCL + (al0.x + amv.x) * L2E;
                sc[nb][1] = sc[nb][1] * SCL + (al0.y + amv.y) * L2E;
                sc[nb][2] = sc[nb][2] * SCL + (al1.x + amv.x) * L2E;
                sc[nb][3] = sc[nb][3] * SCL + (al1.y + amv.y) * L2E;
                if (diag) {
                    int kc0 = k0 + nb * 8 + 2 * l;
                    if (kc0     > qrow)     sc[nb][0] = -1e9f;
                    if (kc0 + 1 > qrow)     sc[nb][1] = -1e9f;
                    if (kc0     > qrow + 8) sc[nb][2] = -1e9f;
                    if (kc0 + 1 > qrow + 8) sc[nb][3] = -1e9f;
                }
                mx0 = fmaxf(mx0, fmaxf(sc[nb][0], sc[nb][1]));
                mx1 = fmaxf(mx1, fmaxf(sc[nb][2], sc[nb][3]));
            }
        }

        mx0 = fmaxf(mx0, __shfl_xor_sync(0xffffffffu, mx0, 1));
        mx0 = fmaxf(mx0, __shfl_xor_sync(0xffffffffu, mx0, 2));
        mx1 = fmaxf(mx1, __shfl_xor_sync(0xffffffffu, mx1, 1));
        mx1 = fmaxf(mx1, __shfl_xor_sync(0xffffffffu, mx1, 2));

        float mn0 = fmaxf(m0, mx0), mn1 = fmaxf(m1, mx1);
        float c0 = ex2(m0 - mn0), c1 = ex2(m1 - mn1);
        m0 = mn0; m1 = mn1;

        float rs0 = 0.f, rs1 = 0.f;
        #pragma unroll
        for (int nb = 0; nb < 8; nb++) {
            float p00 = ex2(sc[nb][0] - m0);
            float p01 = ex2(sc[nb][1] - m0);
            float p10 = ex2(sc[nb][2] - m1);
            float p11 = ex2(sc[nb][3] - m1);
            rs0 += p00 + p01;
            rs1 += p10 + p11;
            *(float2*)&sP[(w * 16 + g)     * PST + nb * 8 + 2 * l] =
                make_float2(tf32f(p00), tf32f(p01));
            *(float2*)&sP[(w * 16 + g + 8) * PST + nb * 8 + 2 * l] =
                make_float2(tf32f(p10), tf32f(p11));
        }
        rs0 += __shfl_xor_sync(0xffffffffu, rs0, 1);
        rs0 += __shfl_xor_sync(0xffffffffu, rs0, 2);
        rs1 += __shfl_xor_sync(0xffffffffu, rs1, 1);
        rs1 += __shfl_xor_sync(0xffffffffu, rs1, 2);
        s0 = s0 * c0 + rs0;
        s1 = s1 * c1 + rs1;

        #pragma unroll
        for (int nb = 0; nb < 16; nb++) {
            o[nb][0] *= c0; o[nb][1] *= c0;
            o[nb][2] *= c1; o[nb][3] *= c1;
        }

        // V[kt] ready (K[kt+1] may still be in flight)
        if (has_next)
            asm volatile("cp.async.wait_group 1;\n" ::: "memory");
        else
            asm volatile("cp.async.wait_group 0;\n" ::: "memory");
        __syncthreads();

        // ---- O += P @ V (overlaps in-flight K[kt+1]) ----
        #pragma unroll
        for (int kc = 0; kc < 8; kc++) {
            unsigned a[4];
            a[0] = __float_as_uint(sP[(w * 16 + g)     * PST + kc * 8 + l]);
            a[1] = __float_as_uint(sP[(w * 16 + g + 8) * PST + kc * 8 + l]);
            a[2] = __float_as_uint(sP[(w * 16 + g)     * PST + kc * 8 + l + 4]);
            a[3] = __float_as_uint(sP[(w * 16 + g + 8) * PST + kc * 8 + l + 4]);
            #pragma unroll
            for (int nb = 0; nb < 16; nb++) {
                unsigned b0 = __float_as_uint(sV[(kc * 8 + l)     * VST + nb * 8 + g]);
                unsigned b1 = __float_as_uint(sV[(kc * 8 + l + 4) * VST + nb * 8 + g]);
                mma8(o[nb], a, b0, b1);
            }
        }
        __syncthreads();                      // all V/P reads done
        if (has_next)
            load_tile(sVu, k0 + 64, kvh * HD + VOFF);   // prefetch V[kt+1]
    }

    // ---- epilogue: O /= l, tf32-round, write P8-permuted ctx for Wo GEMM ----
    float inv0 = 1.0f / s0, inv1 = 1.0f / s1;
    size_t row0 = (size_t)(b * SS + qrow);
    const int pos0 = (l < 2) ? 4 * l : 4 * l - 7;
    #pragma unroll
    for (int nb = 0; nb < 16; nb++) {
        size_t cb = h * HD + nb * 8;
        Og[row0 * DIM + cb + pos0]           = tf32f(o[nb][0] * inv0);
        Og[row0 * DIM + cb + pos0 + 2]       = tf32f(o[nb][1] * inv0);
        Og[(row0 + 8) * DIM + cb + pos0]     = tf32f(o[nb][2] * inv1);
        Og[(row0 + 8) * DIM + cb + pos0 + 2] = tf32f(o[nb][3] * inv1);
    }
}

// ---------------------------------------------------------------------------
// Launch
// ---------------------------------------------------------------------------
extern "C" void kernel_launch(void* const* d_in, const int* in_sizes, int n_in,
                              void* d_out, int out_size)
{
    const float* X     = (const float*)d_in[0];
    const float* cosT  = (const float*)d_in[1];
    const float* sinT  = (const float*)d_in[2];
    const float* alibi = (const float*)d_in[3];
    const float* amask = (const float*)d_in[4];
    const float* wq    = (const float*)d_in[5];
    const float* wk    = (const float*)d_in[6];
    const float* wv    = (const float*)d_in[7];
    const float* wo    = (const float*)d_in[8];
    float* out = (float*)d_out;

    float *Xr, *Wt, *Wot, *QKV, *C;
    cudaGetSymbolAddress((void**)&Xr,  gXr);
    cudaGetSymbolAddress((void**)&Wt,  gWt);
    cudaGetSymbolAddress((void**)&Wot, gWot);
    cudaGetSymbolAddress((void**)&QKV, gQKV);
    cudaGetSymbolAddress((void**)&C,   gC);

    cudaFuncSetAttribute(tf32_gemm2<true>,
                         cudaFuncAttributeMaxDynamicSharedMemorySize, GEMM2_SMEM);
    cudaFuncSetAttribute(tf32_gemm2<false>,
                         cudaFuncAttributeMaxDynamicSharedMemorySize, GEMM2_SMEM);
    cudaFuncSetAttribute(attn_mma,
                         cudaFuncAttributeMaxDynamicSharedMemorySize, ATTN_SMEM);

    // 1
    permute_round_x<<<ROWS * (DIM / 8) / 256, 256>>>(X, Xr);
    // 2
    wpack_all<<<dim3(64, 64, 4), dim3(32, 8)>>>(wq, wk, wv, wo, Wt, Wot);
    // 3: fused QKV projection, outputs tf32-rounded
    tf32_gemm2<true><<<dim3(QKVD / 128, ROWS / 128), 128, GEMM2_SMEM>>>(
        Xr, Wt, QKV, QKVD, DIM);
    // 4,5: RoPE (d-permute + tf32 round) on Q and K
    rope_kernel<<<(ROWS * NH * 8 + 255) / 256, 256>>>(QKV, cosT, sinT, 4, QKVD);
    rope_kernel<<<(ROWS * KVH * 8 + 255) / 256, 256>>>(QKV + KOFF, cosT, sinT, 2, QKVD);
    // 6: pipelined flash attention
    attn_mma<<<dim3(SS / 64, BB * NH), 128, ATTN_SMEM>>>(QKV, alibi, amask, C);
    // 7: output projection (unrounded output)
    tf32_gemm2<false><<<dim3(DIM / 128, ROWS / 128), 128, GEMM2_SMEM>>>(
        C, Wot, out, DIM, DIM);
}

// round 10
// speedup vs baseline: 1.6633x; 1.3339x over previous
#include <cuda_runtime.h>
#include <cuda_fp16.h>
#include <cstdint>

// Problem constants
#define BB   2
#define SS   2048
#define DIM  2048
#define NH   16
#define KVH  4
#define HD   128
#define ROWS (BB*SS)          // 4096
#define QKVD 3072             // fused Q|K|V width
#define KOFF 2048
#define VOFF 2560

// ---------------------------------------------------------------------------
// Scratch (static device globals — no allocation)
// ---------------------------------------------------------------------------
__device__ __half gXr [(size_t)ROWS * DIM];    // X, fp16, k16-interleaved
__device__ __half gWt [(size_t)QKVD * DIM];    // [Wq|Wk|Wv]^T, fp16, k16-int
__device__ __half gWot[(size_t)DIM * DIM];     // Wo^T, fp16, k16-int
__device__ float  gQKV[(size_t)ROWS * QKVD];   // tf32-rounded; Q,K roped+P8
__device__ __half gC  [(size_t)ROWS * DIM];    // attn ctx, fp16, k16-int

// ---------------------------------------------------------------------------
// helpers
// ---------------------------------------------------------------------------
__device__ __forceinline__ unsigned tf32u(float x) {
    unsigned u;
    asm("cvt.rna.tf32.f32 %0, %1;" : "=r"(u) : "f"(x));
    return u;
}
__device__ __forceinline__ float tf32f(float x) { return __uint_as_float(tf32u(x)); }
__device__ __forceinline__ float ex2(float x) {
    float r;
    asm("ex2.approx.ftz.f32 %0, %1;" : "=f"(r) : "f"(x));
    return r;
}

// k16 pair-interleave: phys pair p holds logical pair j = (p>>1) + (p&1)*4.
// Thread l's LDS.64 at pair 2l..2l+1 -> logical pairs l and l+4 = k {2l,2l+1,2l+8,2l+9}.
__global__ void permute_round_x(const float* __restrict__ in,
                                __half* __restrict__ out) {
    int idx = blockIdx.x * blockDim.x + threadIdx.x;   // one 16-group
    if (idx >= ROWS * (DIM / 16)) return;
    const float4* s = (const float4*)(in + (size_t)idx * 16);
    float4 v0 = s[0], v1 = s[1], v2 = s[2], v3 = s[3];
    __half2* d = (__half2*)(out + (size_t)idx * 16);
    d[0] = __floats2half2_rn(v0.x, v0.y);   // j0
    d[1] = __floats2half2_rn(v2.x, v2.y);   // j4
    d[2] = __floats2half2_rn(v0.z, v0.w);   // j1
    d[3] = __floats2half2_rn(v2.z, v2.w);   // j5
    d[4] = __floats2half2_rn(v1.x, v1.y);   // j2
    d[5] = __floats2half2_rn(v3.x, v3.y);   // j6
    d[6] = __floats2half2_rn(v1.z, v1.w);   // j3
    d[7] = __floats2half2_rn(v3.z, v3.w);   // j7
}

// Transpose-pack all 4 weights: W[k][n] -> out[n][k16-interleaved], fp16.
__global__ void wpack_all(const float* __restrict__ wq,
                          const float* __restrict__ wk,
                          const float* __restrict__ wv,
                          const float* __restrict__ wo,
                          __half* __restrict__ Wt, __half* __restrict__ Wot) {
    const float* W;
    __half* out;
    int Nw;
    int z = blockIdx.z;
    if (z == 0)      { W = wq; out = Wt;                         Nw = 2048; }
    else if (z == 1) { W = wo; out = Wot;                        Nw = 2048; }
    else if (z == 2) { W = wk; out = Wt + (size_t)2048 * 2048;   Nw = 512;  }
    else             { W = wv; out = Wt + (size_t)2560 * 2048;   Nw = 512;  }
    int n0 = blockIdx.x * 32;
    if (n0 >= Nw) return;

    __shared__ float t[32][33];
    int tx = threadIdx.x, ty = threadIdx.y;
    int k0 = blockIdx.y * 32;
    #pragma unroll
    for (int i = 0; i < 4; i++)
        t[ty + 8 * i][tx] = W[(size_t)(k0 + ty + 8 * i) * Nw + n0 + tx];
    __syncthreads();
    // phys position tx within 32-k block -> logical source k
    int q = tx & 15, grp = tx >> 4;
    int p = q >> 1, bit = q & 1;
    int j = (p >> 1) + (p & 1) * 4;
    int ksrc = (grp << 4) + 2 * j + bit;
    #pragma unroll
    for (int i = 0; i < 4; i++)
        out[(size_t)(n0 + ty + 8 * i) * 2048 + k0 + tx] =
            __float2half_rn(t[ksrc][ty + 8 * i]);
}

// ---------------------------------------------------------------------------
// FP16 tensor-core GEMM: C[M,N] = A[M,K] @ Bt[N,K]^T, fp32 accum.
// 128x128 block, 4 warps (2x2), warp tile 64x64, BK=32, cp.async dbuf.
// m16n8k16; all fragment loads are conflict-free LDS.64 (row stride 160 B).
// ---------------------------------------------------------------------------
#define HST 80                               // fp16 units per smem row
#define HGEMM_SMEM (2 * 2 * 128 * HST * 2)   // 81920 B

__device__ __forceinline__ void cp16(unsigned dst, const void* src) {
    asm volatile("cp.async.cg.shared.global [%0], [%1], 16;\n"
                 :: "r"(dst), "l"(src));
}

__device__ __forceinline__ void mma16(float* c, const unsigned* a,
                                      unsigned b0, unsigned b1) {
    asm volatile(
        "mma.sync.aligned.m16n8k16.row.col.f32.f16.f16.f32 "
        "{%0,%1,%2,%3}, {%4,%5,%6,%7}, {%8,%9}, {%0,%1,%2,%3};\n"
        : "+f"(c[0]), "+f"(c[1]), "+f"(c[2]), "+f"(c[3])
        : "r"(a[0]), "r"(a[1]), "r"(a[2]), "r"(a[3]), "r"(b0), "r"(b1));
}

// legacy tf32 mma (attention)
__device__ __forceinline__ void mma8(float* c, const unsigned* a,
                                     unsigned b0, unsigned b1) {
    asm volatile(
        "mma.sync.aligned.m16n8k8.row.col.f32.tf32.tf32.f32 "
        "{%0,%1,%2,%3}, {%4,%5,%6,%7}, {%8,%9}, {%0,%1,%2,%3};\n"
        : "+f"(c[0]), "+f"(c[1]), "+f"(c[2]), "+f"(c[3])
        : "r"(a[0]), "r"(a[1]), "r"(a[2]), "r"(a[3]), "r"(b0), "r"(b1));
}

template <bool RND>
__global__ __launch_bounds__(128) void h16_gemm(
    const __half* __restrict__ A, const __half* __restrict__ Bt,
    float* __restrict__ C, int N, int K)
{
    extern __shared__ __half hsm[];
    __half* As = hsm;                     // [2][128][HST]
    __half* Bs = hsm + 2 * 128 * HST;     // [2][128][HST]

    const int tid  = threadIdx.x;
    const int lane = tid & 31;
    const int w    = tid >> 5;
    const int g    = lane >> 2;
    const int l    = lane & 3;
    const int wm   = (w >> 1) * 64;
    const int wn   = (w & 1) * 64;
    const long bm  = (long)blockIdx.y * 128;
    const long bn  = (long)blockIdx.x * 128;

    const unsigned sAu = (unsigned)__cvta_generic_to_shared(As);
    const unsigned sBu = (unsigned)__cvta_generic_to_shared(Bs);

    // fill mapping: 32 rows x 4 chunks(16B=8 fp16) per pass, 4 passes
    const int rt = tid >> 2;              // 0..31
    const int ct = tid & 3;               // chunk
    const __half* Abase = A  + (bm + rt) * K + ct * 8;
    const __half* Bbase = Bt + (bn + rt) * K + ct * 8;

    float acc[4][8][4];
    #pragma unroll
    for (int mt = 0; mt < 4; mt++)
        #pragma unroll
        for (int nt = 0; nt < 8; nt++)
            #pragma unroll
            for (int j = 0; j < 4; j++) acc[mt][nt][j] = 0.f;

    const int niter = K / 32;

    auto issue = [&](int it, int buf) {
        long k0 = (long)it * 32;
        #pragma unroll
        for (int p = 0; p < 4; p++)
            cp16(sAu + (unsigned)(((buf * 128 + rt + 32 * p) * HST + ct * 8) * 2),
                 Abase + (long)p * 32 * K + k0);
        #pragma unroll
        for (int p = 0; p < 4; p++)
            cp16(sBu + (unsigned)(((buf * 128 + rt + 32 * p) * HST + ct * 8) * 2),
                 Bbase + (long)p * 32 * K + k0);
        asm volatile("cp.async.commit_group;\n");
    };

    issue(0, 0);

    for (int it = 0; it < niter; it++) {
        const int buf = it & 1;
        if (it + 1 < niter) {
            issue(it + 1, buf ^ 1);
            asm volatile("cp.async.wait_group 1;\n");
        } else {
            asm volatile("cp.async.wait_group 0;\n");
        }
        __syncthreads();

        const __half* Ab = As + buf * 128 * HST;
        const __half* Bb = Bs + buf * 128 * HST;

        #pragma unroll
        for (int kk = 0; kk < 2; kk++) {      // two k16 groups per stage
            uint2 alo[4], ahi[4], bv[8];
            #pragma unroll
            for (int mt = 0; mt < 4; mt++) {
                alo[mt] = *(const uint2*)&Ab[(wm + mt * 16 + g)     * HST + kk * 16 + 4 * l];
                ahi[mt] = *(const uint2*)&Ab[(wm + mt * 16 + g + 8) * HST + kk * 16 + 4 * l];
            }
            #pragma unroll
            for (int nt = 0; nt < 8; nt++)
                bv[nt] = *(const uint2*)&Bb[(wn + nt * 8 + g) * HST + kk * 16 + 4 * l];

            #pragma unroll
            for (int mt = 0; mt < 4; mt++) {
                unsigned a[4] = {alo[mt].x, ahi[mt].x, alo[mt].y, ahi[mt].y};
                #pragma unroll
                for (int nt = 0; nt < 8; nt++)
                    mma16(acc[mt][nt], a, bv[nt].x, bv[nt].y);
            }
        }
        __syncthreads();
    }

    #pragma unroll
    for (int mt = 0; mt < 4; mt++)
        #pragma unroll
        for (int nt = 0; nt < 8; nt++) {
            const float* c = acc[mt][nt];
            long row = bm + wm + mt * 16 + g;
            long col = bn + wn + nt * 8 + 2 * l;
            if (RND) {
                *(float2*)&C[row * N + col]       = make_float2(tf32f(c[0]), tf32f(c[1]));
                *(float2*)&C[(row + 8) * N + col] = make_float2(tf32f(c[2]), tf32f(c[3]));
            } else {
                *(float2*)&C[row * N + col]       = make_float2(c[0], c[1]);
                *(float2*)&C[(row + 8) * N + col] = make_float2(c[2], c[3]);
            }
        }
}

// ---------------------------------------------------------------------------
// RoPE in-place on Q/K, emitting d-PERMUTED 8-group layout {0,4,1,5,2,6,3,7},
// outputs tf32-rounded. Each thread owns whole logical groups (t, t+8).
// ---------------------------------------------------------------------------
__global__ void rope_kernel(float* __restrict__ x,
                            const float* __restrict__ cosT,
                            const float* __restrict__ sinT,
                            int nh_shift, int stride)
{
    int idx = blockIdx.x * blockDim.x + threadIdx.x;
    int nheads = 1 << nh_shift;
    int total = ROWS * nheads * 8;
    if (idx >= total) return;
    int t = idx & 7;
    int h = (idx >> 3) & (nheads - 1);
    int r = idx >> (3 + nh_shift);
    int s = r & (SS - 1);

    const float* cs = cosT + s * HD + 8 * t;
    const float* sn = sinT + s * HD + 8 * t;
    float* p = x + (size_t)r * stride + h * HD + 8 * t;

    float a[8], bv[8];
    *(float4*)(a)      = *(const float4*)(p);
    *(float4*)(a + 4)  = *(const float4*)(p + 4);
    *(float4*)(bv)     = *(const float4*)(p + 64);
    *(float4*)(bv + 4) = *(const float4*)(p + 68);

    float oa[8], ob[8];
    #pragma unroll
    for (int j = 0; j < 8; j++) {
        float c0 = cs[j],      s0 = sn[j];
        float c1 = cs[64 + j], s1 = sn[64 + j];
        oa[j] = tf32f(a[j] * c0 - bv[j] * s0);
        ob[j] = tf32f(bv[j] * c1 + a[j] * s1);
    }
    float wa[8], wb[8];
    #pragma unroll
    for (int j = 0; j < 4; j++) {
        wa[2 * j] = oa[j];  wa[2 * j + 1] = oa[j + 4];
        wb[2 * j] = ob[j];  wb[2 * j + 1] = ob[j + 4];
    }
    *(float4*)(p)      = *(float4*)(wa);
    *(float4*)(p + 4)  = *(float4*)(wa + 4);
    *(float4*)(p + 64) = *(float4*)(wb);
    *(float4*)(p + 68) = *(float4*)(wb + 4);
}

// ---------------------------------------------------------------------------
// cp.async-pipelined tensor-core flash attention (R8, proven).
// Epilogue now writes fp16 k16-interleaved ctx for the fp16 Wo GEMM.
// ---------------------------------------------------------------------------
#define KST 136
#define VST 136
#define PST 68
#define ATTN_SMEM ((64*KST + 64*VST + 64*PST) * 4)   // 87040 B

__global__ __launch_bounds__(128) void attn_mma(
    const float* __restrict__ QKVg,
    const float* __restrict__ alibi, const float* __restrict__ amask,
    __half* __restrict__ Og)
{
    extern __shared__ float smn[];
    float* sK = smn;              // [64][136]
    float* sV = smn + 64 * KST;   // [64][136]  (also Q staging at start)
    float* sP = sV + 64 * VST;    // [64][68]

    const unsigned sKu = (unsigned)__cvta_generic_to_shared(sK);
    const unsigned sVu = (unsigned)__cvta_generic_to_shared(sV);

    const int tid  = threadIdx.x;
    const int lane = tid & 31;
    const int w    = tid >> 5;
    const int g    = lane >> 2;
    const int l    = lane & 3;
    const int bh   = blockIdx.y;
    const int b    = bh >> 4;
    const int h    = bh & 15;
    const int kvh  = h >> 2;
    const int bxr  = gridDim.x - 1 - blockIdx.x;   // heavy blocks first
    const int q0   = bxr * 64;
    const int ktiles = bxr + 1;

    auto load_tile = [&](unsigned dstu, int row0, int coloff) {
        #pragma unroll
        for (int it = 0; it < 16; it++) {
            int i = tid + it * 128;
            int r = i >> 5, c4 = (i & 31) << 2;
            cp16(dstu + (unsigned)((r * KST + c4) * 4),
                 &QKVg[(size_t)(b * SS + row0 + r) * QKVD + coloff + c4]);
        }
        asm volatile("cp.async.commit_group;\n" ::: "memory");
    };

    // stage Q into sV region; K[0] into sK
    load_tile(sVu, q0, h * HD);
    load_tile(sKu, 0, kvh * HD + KOFF);
    asm volatile("cp.async.wait_group 1;\n" ::: "memory");   // Q done
    __syncthreads();

    unsigned qf[16][4];
    #pragma unroll
    for (int kc = 0; kc < 16; kc++) {
        float2 q0v = *(const float2*)&sV[(w * 16 + g)     * VST + kc * 8 + 2 * l];
        float2 q1v = *(const float2*)&sV[(w * 16 + g + 8) * VST + kc * 8 + 2 * l];
        qf[kc][0] = __float_as_uint(q0v.x);
        qf[kc][1] = __float_as_uint(q1v.x);
        qf[kc][2] = __float_as_uint(q0v.y);
        qf[kc][3] = __float_as_uint(q1v.y);
    }
    __syncthreads();
    load_tile(sVu, 0, kvh * HD + VOFF);   // V[0]

    const float L2E = 1.4426950408889634f;
    const float SCL = 0.08838834764831845f * L2E;

    float m0 = -1e30f, m1 = -1e30f, s0 = 0.f, s1 = 0.f;
    float o[16][4];
    #pragma unroll
    for (int i = 0; i < 16; i++)
        #pragma unroll
        for (int j = 0; j < 4; j++) o[i][j] = 0.f;

    const int qrow = q0 + w * 16 + g;

    for (int kt = 0; kt < ktiles; kt++) {
        const int k0 = kt * 64;
        const bool has_next = (kt + 1 < ktiles);

        asm volatile("cp.async.wait_group 1;\n" ::: "memory");   // K[kt] ready
        __syncthreads();

        // ---- QK^T (overlaps in-flight V[kt]) ----
        float sc[8][4];
        #pragma unroll
        for (int nb = 0; nb < 8; nb++)
            #pragma unroll
            for (int j = 0; j < 4; j++) sc[nb][j] = 0.f;

        #pragma unroll
        for (int kc = 0; kc < 16; kc++) {
            #pragma unroll
            for (int nb = 0; nb < 8; nb++) {
                float2 kv2 = *(const float2*)&sK[(nb * 8 + g) * KST + kc * 8 + 2 * l];
                mma8(sc[nb], qf[kc],
                     __float_as_uint(kv2.x), __float_as_uint(kv2.y));
            }
        }
        __syncthreads();
        if (has_next)
            load_tile(sKu, k0 + 64, kvh * HD + KOFF);

        // ---- scale + alibi + mask + causal (log2 domain) ----
        const bool diag = (k0 == q0);
        float mx0 = -1e30f, mx1 = -1e30f;
        {
            const float* alr = &alibi[((size_t)b * SS + qrow) * SS + k0 + 2 * l];
            const float* amr = &amask[b * SS + k0 + 2 * l];
            #pragma unroll
            for (int nb = 0; nb < 8; nb++) {
                float2 amv = *(const float2*)(amr + nb * 8);
                float2 al0 = *(const float2*)(alr + nb * 8);
                float2 al1 = *(const float2*)(alr + nb * 8 + 8 * SS);
                sc[nb][0] = sc[nb][0] * SCL + (al0.x + amv.x) * L2E;
                sc[nb][1] = sc[nb][1] * SCL + (al0.y + amv.y) * L2E;
                sc[nb][2] = sc[nb][2] * SCL + (al1.x + amv.x) * L2E;
                sc[nb][3] = sc[nb][3] * SCL + (al1.y + amv.y) * L2E;
                if (diag) {
                    int kc0 = k0 + nb * 8 + 2 * l;
                    if (kc0     > qrow)     sc[nb][0] = -1e9f;
                    if (kc0 + 1 > qrow)     sc[nb][1] = -1e9f;
                    if (kc0     > qrow + 8) sc[nb][2] = -1e9f;
                    if (kc0 + 1 > qrow + 8) sc[nb][3] = -1e9f;
                }
                mx0 = fmaxf(mx0, fmaxf(sc[nb][0], sc[nb][1]));
                mx1 = fmaxf(mx1, fmaxf(sc[nb][2], sc[nb][3]));
            }
        }

        mx0 = fmaxf(mx0, __shfl_xor_sync(0xffffffffu, mx0, 1));
        mx0 = fmaxf(mx0, __shfl_xor_sync(0xffffffffu, mx0, 2));
        mx1 = fmaxf(mx1, __shfl_xor_sync(0xffffffffu, mx1, 1));
        mx1 = fmaxf(mx1, __shfl_xor_sync(0xffffffffu, mx1, 2));

        float mn0 = fmaxf(m0, mx0), mn1 = fmaxf(m1, mx1);
        float c0 = ex2(m0 - mn0), c1 = ex2(m1 - mn1);
        m0 = mn0; m1 = mn1;

        float rs0 = 0.f, rs1 = 0.f;
        #pragma unroll
        for (int nb = 0; nb < 8; nb++) {
            float p00 = ex2(sc[nb][0] - m0);
            float p01 = ex2(sc[nb][1] - m0);
            float p10 = ex2(sc[nb][2] - m1);
            float p11 = ex2(sc[nb][3] - m1);
            rs0 += p00 + p01;
            rs1 += p10 + p11;
            *(float2*)&sP[(w * 16 + g)     * PST + nb * 8 + 2 * l] =
                make_float2(tf32f(p00), tf32f(p01));
            *(float2*)&sP[(w * 16 + g + 8) * PST + nb * 8 + 2 * l] =
                make_float2(tf32f(p10), tf32f(p11));
        }
        rs0 += __shfl_xor_sync(0xffffffffu, rs0, 1);
        rs0 += __shfl_xor_sync(0xffffffffu, rs0, 2);
        rs1 += __shfl_xor_sync(0xffffffffu, rs1, 1);
        rs1 += __shfl_xor_sync(0xffffffffu, rs1, 2);
        s0 = s0 * c0 + rs0;
        s1 = s1 * c1 + rs1;

        #pragma unroll
        for (int nb = 0; nb < 16; nb++) {
            o[nb][0] *= c0; o[nb][1] *= c0;
            o[nb][2] *= c1; o[nb][3] *= c1;
        }

        if (has_next)
            asm volatile("cp.async.wait_group 1;\n" ::: "memory");   // V[kt]
        else
            asm volatile("cp.async.wait_group 0;\n" ::: "memory");
        __syncthreads();

        // ---- O += P @ V (overlaps in-flight K[kt+1]) ----
        #pragma unroll
        for (int kc = 0; kc < 8; kc++) {
            unsigned a[4];
            a[0] = __float_as_uint(sP[(w * 16 + g)     * PST + kc * 8 + l]);
            a[1] = __float_as_uint(sP[(w * 16 + g + 8) * PST + kc * 8 + l]);
            a[2] = __float_as_uint(sP[(w * 16 + g)     * PST + kc * 8 + l + 4]);
            a[3] = __float_as_uint(sP[(w * 16 + g + 8) * PST + kc * 8 + l + 4]);
            #pragma unroll
            for (int nb = 0; nb < 16; nb++) {
                unsigned b0 = __float_as_uint(sV[(kc * 8 + l)     * VST + nb * 8 + g]);
                unsigned b1 = __float_as_uint(sV[(kc * 8 + l + 4) * VST + nb * 8 + g]);
                mma8(o[nb], a, b0, b1);
            }
        }
        __syncthreads();
        if (has_next)
            load_tile(sVu, k0 + 64, kvh * HD + VOFF);
    }

    // ---- epilogue: O /= l, write fp16 k16-interleaved ctx for Wo GEMM ----
    // Thread holds cols nb*8 + 2l, 2l+1. Within the 16-group (nb>>1):
    // logical pair j = (nb&1)*4 + l -> phys pair 2l + (nb&1) -> offset 4l + 2(nb&1).
    float inv0 = 1.0f / s0, inv1 = 1.0f / s1;
    size_t row0 = (size_t)(b * SS + qrow);
    #pragma unroll
    for (int nb = 0; nb < 16; nb++) {
        size_t cb = h * HD + (nb >> 1) * 16 + 4 * l + 2 * (nb & 1);
        *(__half2*)&Og[row0 * DIM + cb] =
            __floats2half2_rn(o[nb][0] * inv0, o[nb][1] * inv0);
        *(__half2*)&Og[(row0 + 8) * DIM + cb] =
            __floats2half2_rn(o[nb][2] * inv1, o[nb][3] * inv1);
    }
}

// ---------------------------------------------------------------------------
// Launch
// ---------------------------------------------------------------------------
extern "C" void kernel_launch(void* const* d_in, const int* in_sizes, int n_in,
                              void* d_out, int out_size)
{
    const float* X     = (const float*)d_in[0];
    const float* cosT  = (const float*)d_in[1];
    const float* sinT  = (const float*)d_in[2];
    const float* alibi = (const float*)d_in[3];
    const float* amask = (const float*)d_in[4];
    const float* wq    = (const float*)d_in[5];
    const float* wk    = (const float*)d_in[6];
    const float* wv    = (const float*)d_in[7];
    const float* wo    = (const float*)d_in[8];
    float* out = (float*)d_out;

    __half *Xr, *Wt, *Wot, *C;
    float *QKV;
    cudaGetSymbolAddress((void**)&Xr,  gXr);
    cudaGetSymbolAddress((void**)&Wt,  gWt);
    cudaGetSymbolAddress((void**)&Wot, gWot);
    cudaGetSymbolAddress((void**)&QKV, gQKV);
    cudaGetSymbolAddress((void**)&C,   gC);

    cudaFuncSetAttribute(h16_gemm<true>,
                         cudaFuncAttributeMaxDynamicSharedMemorySize, HGEMM_SMEM);
    cudaFuncSetAttribute(h16_gemm<false>,
                         cudaFuncAttributeMaxDynamicSharedMemorySize, HGEMM_SMEM);
    cudaFuncSetAttribute(attn_mma,
                         cudaFuncAttributeMaxDynamicSharedMemorySize, ATTN_SMEM);

    // 1: X -> fp16 k16-interleaved
    permute_round_x<<<ROWS * (DIM / 16) / 256, 256>>>(X, Xr);
    // 2: all weight packs (fp16, transposed, k16-interleaved)
    wpack_all<<<dim3(64, 64, 4), dim3(32, 8)>>>(wq, wk, wv, wo, Wt, Wot);
    // 3: fused QKV projection (fp16 MMA, tf32-rounded fp32 out)
    h16_gemm<true><<<dim3(QKVD / 128, ROWS / 128), 128, HGEMM_SMEM>>>(
        Xr, Wt, QKV, QKVD, DIM);
    // 4,5: RoPE (d-permute + tf32 round) on Q and K
    rope_kernel<<<(ROWS * NH * 8 + 255) / 256, 256>>>(QKV, cosT, sinT, 4, QKVD);
    rope_kernel<<<(ROWS * KVH * 8 + 255) / 256, 256>>>(QKV + KOFF, cosT, sinT, 2, QKVD);
    // 6: pipelined flash attention (fp16 interleaved ctx out)
    attn_mma<<<dim3(SS / 64, BB * NH), 128, ATTN_SMEM>>>(QKV, alibi, amask, C);
    // 7: output projection (fp16 MMA, fp32 out)
    h16_gemm<false><<<dim3(DIM / 128, ROWS / 128), 128, HGEMM_SMEM>>>(
        C, Wot, out, DIM, DIM);
}

// round 12
// speedup vs baseline: 1.7262x; 1.0379x over previous
#include <cuda_runtime.h>
#include <cuda_fp16.h>
#include <cstdint>

// Problem constants
#define BB   2
#define SS   2048
#define DIM  2048
#define NH   16
#define KVH  4
#define HD   128
#define ROWS (BB*SS)          // 4096
#define QKVD 3072             // fused Q|K|V width
#define KOFF 2048
#define VOFF 2560

// ---------------------------------------------------------------------------
// Scratch (static device globals — no allocation)
// ---------------------------------------------------------------------------
__device__ __half gXr [(size_t)ROWS * DIM];    // X, fp16, k16-interleaved
__device__ __half gWt [(size_t)QKVD * DIM];    // [Wq|Wk|Wv]^T, fp16, k16-int
__device__ __half gWot[(size_t)DIM * DIM];     // Wo^T, fp16, k16-int
__device__ __half gQKV[(size_t)ROWS * QKVD];   // fp16; Q,K roped+d-interleaved
__device__ __half gVt [(size_t)BB * KVH * HD * SS];  // V^T, key-interleaved
__device__ __half gC  [(size_t)ROWS * DIM];    // attn ctx, fp16, k16-int

// ---------------------------------------------------------------------------
// helpers
// ---------------------------------------------------------------------------
__device__ __forceinline__ float ex2(float x) {
    float r;
    asm("ex2.approx.ftz.f32 %0, %1;" : "=f"(r) : "f"(x));
    return r;
}

// k16 pair-interleave: phys pair p holds logical pair j = (p>>1) + (p&1)*4.
__global__ void permute_round_x(const float* __restrict__ in,
                                __half* __restrict__ out) {
    int idx = blockIdx.x * blockDim.x + threadIdx.x;   // one 16-group
    if (idx >= ROWS * (DIM / 16)) return;
    const float4* s = (const float4*)(in + (size_t)idx * 16);
    float4 v0 = s[0], v1 = s[1], v2 = s[2], v3 = s[3];
    __half2* d = (__half2*)(out + (size_t)idx * 16);
    d[0] = __floats2half2_rn(v0.x, v0.y);   // j0
    d[1] = __floats2half2_rn(v2.x, v2.y);   // j4
    d[2] = __floats2half2_rn(v0.z, v0.w);   // j1
    d[3] = __floats2half2_rn(v2.z, v2.w);   // j5
    d[4] = __floats2half2_rn(v1.x, v1.y);   // j2
    d[5] = __floats2half2_rn(v3.x, v3.y);   // j6
    d[6] = __floats2half2_rn(v1.z, v1.w);   // j3
    d[7] = __floats2half2_rn(v3.z, v3.w);   // j7
}

// Transpose-pack all 4 weights: W[k][n] -> out[n][k16-interleaved], fp16.
__global__ void wpack_all(const float* __restrict__ wq,
                          const float* __restrict__ wk,
                          const float* __restrict__ wv,
                          const float* __restrict__ wo,
                          __half* __restrict__ Wt, __half* __restrict__ Wot) {
    const float* W;
    __half* out;
    int Nw;
    int z = blockIdx.z;
    if (z == 0)      { W = wq; out = Wt;                         Nw = 2048; }
    else if (z == 1) { W = wo; out = Wot;                        Nw = 2048; }
    else if (z == 2) { W = wk; out = Wt + (size_t)2048 * 2048;   Nw = 512;  }
    else             { W = wv; out = Wt + (size_t)2560 * 2048;   Nw = 512;  }
    int n0 = blockIdx.x * 32;
    if (n0 >= Nw) return;

    __shared__ float t[32][33];
    int tx = threadIdx.x, ty = threadIdx.y;
    int k0 = blockIdx.y * 32;
    #pragma unroll
    for (int i = 0; i < 4; i++)
        t[ty + 8 * i][tx] = W[(size_t)(k0 + ty + 8 * i) * Nw + n0 + tx];
    __syncthreads();
    int q = tx & 15, grp = tx >> 4;
    int p = q >> 1, bit = q & 1;
    int j = (p >> 1) + (p & 1) * 4;
    int ksrc = (grp << 4) + 2 * j + bit;
    #pragma unroll
    for (int i = 0; i < 4; i++)
        out[(size_t)(n0 + ty + 8 * i) * 2048 + k0 + tx] =
            __float2half_rn(t[ksrc][ty + 8 * i]);
}

// Transpose V: gQKV V-region [s][d] -> gVt[(b,kvh,d)][key-interleaved s], fp16.
__global__ void vtrans(const __half* __restrict__ QKV,
                       __half* __restrict__ Vt) {
    __shared__ __half t[32][33];
    int bz = blockIdx.z;              // b*KVH+kvh
    int b = bz >> 2, kvh = bz & 3;
    int s0 = blockIdx.x * 32, d0 = blockIdx.y * 32;
    int tx = threadIdx.x, ty = threadIdx.y;
    #pragma unroll
    for (int i = 0; i < 4; i++)
        t[ty + 8 * i][tx] =
            QKV[(size_t)(b * SS + s0 + ty + 8 * i) * QKVD + VOFF + kvh * HD + d0 + tx];
    __syncthreads();
    int q = tx & 15, grp = tx >> 4;
    int p = q >> 1, bit = q & 1;
    int j = (p >> 1) + (p & 1) * 4;
    int ksrc = (grp << 4) + 2 * j + bit;          // phys tx holds logical key ksrc
    #pragma unroll
    for (int i = 0; i < 4; i++)
        Vt[((size_t)bz * HD + d0 + ty + 8 * i) * SS + s0 + tx] = t[ksrc][ty + 8 * i];
}

// ---------------------------------------------------------------------------
// FP16 tensor-core GEMM (R9, proven): C = A @ Bt^T, fp32 accum.
// OUTH: write fp16 (QKV), else fp32 (final out).
// ---------------------------------------------------------------------------
#define HST 80                               // fp16 units per smem row
#define HGEMM_SMEM (2 * 2 * 128 * HST * 2)   // 81920 B

__device__ __forceinline__ void cp16(unsigned dst, const void* src) {
    asm volatile("cp.async.cg.shared.global [%0], [%1], 16;\n"
                 :: "r"(dst), "l"(src));
}

__device__ __forceinline__ void mma16(float* c, const unsigned* a,
                                      unsigned b0, unsigned b1) {
    asm volatile(
        "mma.sync.aligned.m16n8k16.row.col.f32.f16.f16.f32 "
        "{%0,%1,%2,%3}, {%4,%5,%6,%7}, {%8,%9}, {%0,%1,%2,%3};\n"
        : "+f"(c[0]), "+f"(c[1]), "+f"(c[2]), "+f"(c[3])
        : "r"(a[0]), "r"(a[1]), "r"(a[2]), "r"(a[3]), "r"(b0), "r"(b1));
}

template <bool OUTH>
__global__ __launch_bounds__(128) void h16_gemm(
    const __half* __restrict__ A, const __half* __restrict__ Bt,
    void* __restrict__ Cv, int N, int K)
{
    extern __shared__ __half hsm[];
    __half* As = hsm;                     // [2][128][HST]
    __half* Bs = hsm + 2 * 128 * HST;     // [2][128][HST]

    const int tid  = threadIdx.x;
    const int lane = tid & 31;
    const int w    = tid >> 5;
    const int g    = lane >> 2;
    const int l    = lane & 3;
    const int wm   = (w >> 1) * 64;
    const int wn   = (w & 1) * 64;
    const long bm  = (long)blockIdx.y * 128;
    const long bn  = (long)blockIdx.x * 128;

    const unsigned sAu = (unsigned)__cvta_generic_to_shared(As);
    const unsigned sBu = (unsigned)__cvta_generic_to_shared(Bs);

    const int rt = tid >> 2;              // 0..31
    const int ct = tid & 3;               // 16B chunk
    const __half* Abase = A  + (bm + rt) * K + ct * 8;
    const __half* Bbase = Bt + (bn + rt) * K + ct * 8;

    float acc[4][8][4];
    #pragma unroll
    for (int mt = 0; mt < 4; mt++)
        #pragma unroll
        for (int nt = 0; nt < 8; nt++)
            #pragma unroll
            for (int j = 0; j < 4; j++) acc[mt][nt][j] = 0.f;

    const int niter = K / 32;

    auto issue = [&](int it, int buf) {
        long k0 = (long)it * 32;
        #pragma unroll
        for (int p = 0; p < 4; p++)
            cp16(sAu + (unsigned)(((buf * 128 + rt + 32 * p) * HST + ct * 8) * 2),
                 Abase + (long)p * 32 * K + k0);
        #pragma unroll
        for (int p = 0; p < 4; p++)
            cp16(sBu + (unsigned)(((buf * 128 + rt + 32 * p) * HST + ct * 8) * 2),
                 Bbase + (long)p * 32 * K + k0);
        asm volatile("cp.async.commit_group;\n");
    };

    issue(0, 0);

    for (int it = 0; it < niter; it++) {
        const int buf = it & 1;
        if (it + 1 < niter) {
            issue(it + 1, buf ^ 1);
            asm volatile("cp.async.wait_group 1;\n");
        } else {
            asm volatile("cp.async.wait_group 0;\n");
        }
        __syncthreads();

        const __half* Ab = As + buf * 128 * HST;
        const __half* Bb = Bs + buf * 128 * HST;

        #pragma unroll
        for (int kk = 0; kk < 2; kk++) {
            uint2 alo[4], ahi[4], bv[8];
            #pragma unroll
            for (int mt = 0; mt < 4; mt++) {
                alo[mt] = *(const uint2*)&Ab[(wm + mt * 16 + g)     * HST + kk * 16 + 4 * l];
                ahi[mt] = *(const uint2*)&Ab[(wm + mt * 16 + g + 8) * HST + kk * 16 + 4 * l];
            }
            #pragma unroll
            for (int nt = 0; nt < 8; nt++)
                bv[nt] = *(const uint2*)&Bb[(wn + nt * 8 + g) * HST + kk * 16 + 4 * l];

            #pragma unroll
            for (int mt = 0; mt < 4; mt++) {
                unsigned a[4] = {alo[mt].x, ahi[mt].x, alo[mt].y, ahi[mt].y};
                #pragma unroll
                for (int nt = 0; nt < 8; nt++)
                    mma16(acc[mt][nt], a, bv[nt].x, bv[nt].y);
            }
        }
        __syncthreads();
    }

    #pragma unroll
    for (int mt = 0; mt < 4; mt++)
        #pragma unroll
        for (int nt = 0; nt < 8; nt++) {
            const float* c = acc[mt][nt];
            long row = bm + wm + mt * 16 + g;
            long col = bn + wn + nt * 8 + 2 * l;
            if (OUTH) {
                __half* C = (__half*)Cv;
                *(__half2*)&C[row * N + col]       = __floats2half2_rn(c[0], c[1]);
                *(__half2*)&C[(row + 8) * N + col] = __floats2half2_rn(c[2], c[3]);
            } else {
                float* C = (float*)Cv;
                *(float2*)&C[row * N + col]       = make_float2(c[0], c[1]);
                *(float2*)&C[(row + 8) * N + col] = make_float2(c[2], c[3]);
            }
        }
}

// ---------------------------------------------------------------------------
// RoPE in-place on fp16 Q/K, emitting k16-interleaved d layout.
// ---------------------------------------------------------------------------
__global__ void rope_h(__half* __restrict__ x,
                       const float* __restrict__ cosT,
                       const float* __restrict__ sinT,
                       int nh_shift, int stride)
{
    int idx = blockIdx.x * blockDim.x + threadIdx.x;
    int nheads = 1 << nh_shift;
    int total = ROWS * nheads * 4;
    if (idx >= total) return;
    int t = idx & 3;
    int h = (idx >> 2) & (nheads - 1);
    int r = idx >> (2 + nh_shift);
    int s = r & (SS - 1);

    const float* cs = cosT + s * HD + 16 * t;
    const float* sn = sinT + s * HD + 16 * t;
    __half* p = x + (size_t)r * stride + h * HD + 16 * t;

    __half a[16], bv[16];
    *(uint4*)(a)      = *(const uint4*)(p);
    *(uint4*)(a + 8)  = *(const uint4*)(p + 8);
    *(uint4*)(bv)     = *(const uint4*)(p + 64);
    *(uint4*)(bv + 8) = *(const uint4*)(p + 72);

    float oa[16], ob[16];
    #pragma unroll
    for (int j = 0; j < 16; j++) {
        float av = __half2float(a[j]), bb = __half2float(bv[j]);
        oa[j] = av * cs[j]      - bb * sn[j];
        ob[j] = bb * cs[64 + j] + av * sn[64 + j];
    }
    __half wa[16], wb[16];
    #pragma unroll
    for (int q = 0; q < 16; q++) {
        int pp = q >> 1, bit = q & 1;
        int j = (pp >> 1) + (pp & 1) * 4;
        int src = 2 * j + bit;
        wa[q] = __float2half_rn(oa[src]);
        wb[q] = __float2half_rn(ob[src]);
    }
    *(uint4*)(p)      = *(uint4*)(wa);
    *(uint4*)(p + 8)  = *(uint4*)(wa + 8);
    *(uint4*)(p + 64) = *(uint4*)(wb);
    *(uint4*)(p + 72) = *(uint4*)(wb + 8);
}

// ---------------------------------------------------------------------------
// FP16 cp.async-pipelined flash attention. 64 q-rows, 4 warps, 64-key tiles.
// sK/sQ stride 144 halves (K row = 128 halves DATA; 80 was the R10 bug).
// Word-stride 72 ≡ 8 mod 32 -> conflict-free LDS.64 fragments (bank 8g+2l).
// ---------------------------------------------------------------------------
#define AKST 144         // sK row stride (halves) — row data = 128 halves
#define AVST 80          // sVt row stride (row data = 64 halves)
#define APST 80          // sP row stride (row data = 64 halves)
#define AQST 144         // Q staging stride
#define ATTN_SMEM ((64*AKST + 128*AVST + 64*APST) * 2)   // 49152 B

__global__ __launch_bounds__(128) void attn_h(
    const __half* __restrict__ QKVg, const __half* __restrict__ Vtg,
    const float* __restrict__ alibi, const float* __restrict__ amask,
    __half* __restrict__ Og)
{
    extern __shared__ __half smh[];
    __half* sK  = smh;                      // [64][144]
    __half* sVt = smh + 64 * AKST;          // [128][80]
    __half* sP  = sVt + 128 * AVST;         // [64][80]
    __half* sQ  = sVt;                      // Q staging [64][144] (9216 <= 10240)

    const unsigned sKu  = (unsigned)__cvta_generic_to_shared(sK);
    const unsigned sVtu = (unsigned)__cvta_generic_to_shared(sVt);
    const unsigned sQu  = (unsigned)__cvta_generic_to_shared(sQ);

    const int tid  = threadIdx.x;
    const int lane = tid & 31;
    const int w    = tid >> 5;
    const int g    = lane >> 2;
    const int l    = lane & 3;
    const int bh   = blockIdx.y;
    const int b    = bh >> 4;
    const int h    = bh & 15;
    const int kvh  = h >> 2;
    const int bz   = b * KVH + kvh;
    const int bxr  = gridDim.x - 1 - blockIdx.x;   // heavy blocks first
    const int q0   = bxr * 64;
    const int ktiles = bxr + 1;

    // K tile loader: 64 rows x 256 B (16 chunks/row)
    auto load_k = [&](int k0) {
        #pragma unroll
        for (int it = 0; it < 8; it++) {
            int i = tid + it * 128;
            int r = i >> 4, c = i & 15;
            cp16(sKu + (unsigned)(r * AKST * 2 + c * 16),
                 &QKVg[(size_t)(b * SS + k0 + r) * QKVD + KOFF + kvh * HD + 8 * c]);
        }
        asm volatile("cp.async.commit_group;\n" ::: "memory");
    };
    // V^T tile loader: 128 rows x 128 B (8 chunks/row)
    auto load_v = [&](int k0) {
        #pragma unroll
        for (int it = 0; it < 8; it++) {
            int i = tid + it * 128;
            int r = i >> 3, c = i & 7;
            cp16(sVtu + (unsigned)(r * AVST * 2 + c * 16),
                 &Vtg[((size_t)bz * HD + r) * SS + k0 + 8 * c]);
        }
        asm volatile("cp.async.commit_group;\n" ::: "memory");
    };
    // Q staging: 64 rows x 256 B, stride AQST
    auto load_q = [&]() {
        #pragma unroll
        for (int it = 0; it < 8; it++) {
            int i = tid + it * 128;
            int r = i >> 4, c = i & 15;
            cp16(sQu + (unsigned)(r * AQST * 2 + c * 16),
                 &QKVg[(size_t)(b * SS + q0 + r) * QKVD + h * HD + 8 * c]);
        }
        asm volatile("cp.async.commit_group;\n" ::: "memory");
    };

    load_q();
    load_k(0);
    asm volatile("cp.async.wait_group 1;\n" ::: "memory");   // Q ready
    __syncthreads();

    // lift Q fragments: 8 k16 groups x 4 regs
    unsigned qf[8][4];
    #pragma unroll
    for (int kc = 0; kc < 8; kc++) {
        uint2 lo = *(const uint2*)&sQ[(w * 16 + g)     * AQST + kc * 16 + 4 * l];
        uint2 hi = *(const uint2*)&sQ[(w * 16 + g + 8) * AQST + kc * 16 + 4 * l];
        qf[kc][0] = lo.x; qf[kc][1] = hi.x; qf[kc][2] = lo.y; qf[kc][3] = hi.y;
    }
    __syncthreads();
    load_v(0);

    const float L2E = 1.4426950408889634f;
    const float SCL = 0.08838834764831845f * L2E;

    float m0 = -1e30f, m1 = -1e30f, s0 = 0.f, s1 = 0.f;
    float o[16][4];
    #pragma unroll
    for (int i = 0; i < 16; i++)
        #pragma unroll
        for (int j = 0; j < 4; j++) o[i][j] = 0.f;

    const int qrow = q0 + w * 16 + g;

    for (int kt = 0; kt < ktiles; kt++) {
        const int k0 = kt * 64;
        const bool has_next = (kt + 1 < ktiles);

        asm volatile("cp.async.wait_group 1;\n" ::: "memory");   // K[kt] ready
        __syncthreads();

        // ---- QK^T (overlaps in-flight V[kt]) ----
        float sc[8][4];
        #pragma unroll
        for (int nb = 0; nb < 8; nb++)
            #pragma unroll
            for (int j = 0; j < 4; j++) sc[nb][j] = 0.f;

        #pragma unroll
        for (int kc = 0; kc < 8; kc++) {
            #pragma unroll
            for (int nb = 0; nb < 8; nb++) {
                uint2 kv = *(const uint2*)&sK[(nb * 8 + g) * AKST + kc * 16 + 4 * l];
                mma16(sc[nb], qf[kc], kv.x, kv.y);
            }
        }
        __syncthreads();
        if (has_next) load_k(k0 + 64);

        // ---- scale + alibi + mask + causal (log2 domain) ----
        const bool diag = (k0 == q0);
        float mx0 = -1e30f, mx1 = -1e30f;
        {
            const float* alr = &alibi[((size_t)b * SS + qrow) * SS + k0 + 2 * l];
            const float* amr = &amask[b * SS + k0 + 2 * l];
            #pragma unroll
            for (int nb = 0; nb < 8; nb++) {
                float2 amv = *(const float2*)(amr + nb * 8);
                float2 al0 = *(const float2*)(alr + nb * 8);
                float2 al1 = *(const float2*)(alr + nb * 8 + 8 * SS);
                sc[nb][0] = sc[nb][0] * SCL + (al0.x + amv.x) * L2E;
                sc[nb][1] = sc[nb][1] * SCL + (al0.y + amv.y) * L2E;
                sc[nb][2] = sc[nb][2] * SCL + (al1.x + amv.x) * L2E;
                sc[nb][3] = sc[nb][3] * SCL + (al1.y + amv.y) * L2E;
                if (diag) {
                    int kc0 = k0 + nb * 8 + 2 * l;
                    if (kc0     > qrow)     sc[nb][0] = -1e9f;
                    if (kc0 + 1 > qrow)     sc[nb][1] = -1e9f;
                    if (kc0     > qrow + 8) sc[nb][2] = -1e9f;
                    if (kc0 + 1 > qrow + 8) sc[nb][3] = -1e9f;
                }
                mx0 = fmaxf(mx0, fmaxf(sc[nb][0], sc[nb][1]));
                mx1 = fmaxf(mx1, fmaxf(sc[nb][2], sc[nb][3]));
            }
        }

        mx0 = fmaxf(mx0, __shfl_xor_sync(0xffffffffu, mx0, 1));
        mx0 = fmaxf(mx0, __shfl_xor_sync(0xffffffffu, mx0, 2));
        mx1 = fmaxf(mx1, __shfl_xor_sync(0xffffffffu, mx1, 1));
        mx1 = fmaxf(mx1, __shfl_xor_sync(0xffffffffu, mx1, 2));

        float mn0 = fmaxf(m0, mx0), mn1 = fmaxf(m1, mx1);
        float c0 = ex2(m0 - mn0), c1 = ex2(m1 - mn1);
        m0 = mn0; m1 = mn1;

        // ---- p = 2^(sc-m), row sums, store P fp16 key-interleaved ----
        float rs0 = 0.f, rs1 = 0.f;
        #pragma unroll
        for (int nb = 0; nb < 8; nb++) {
            float p00 = ex2(sc[nb][0] - m0);
            float p01 = ex2(sc[nb][1] - m0);
            float p10 = ex2(sc[nb][2] - m1);
            float p11 = ex2(sc[nb][3] - m1);
            rs0 += p00 + p01;
            rs1 += p10 + p11;
            int off = (nb >> 1) * 16 + 4 * l + 2 * (nb & 1);
            *(__half2*)&sP[(w * 16 + g)     * APST + off] = __floats2half2_rn(p00, p01);
            *(__half2*)&sP[(w * 16 + g + 8) * APST + off] = __floats2half2_rn(p10, p11);
        }
        rs0 += __shfl_xor_sync(0xffffffffu, rs0, 1);
        rs0 += __shfl_xor_sync(0xffffffffu, rs0, 2);
        rs1 += __shfl_xor_sync(0xffffffffu, rs1, 1);
        rs1 += __shfl_xor_sync(0xffffffffu, rs1, 2);
        s0 = s0 * c0 + rs0;
        s1 = s1 * c1 + rs1;

        #pragma unroll
        for (int nb = 0; nb < 16; nb++) {
            o[nb][0] *= c0; o[nb][1] *= c0;
            o[nb][2] *= c1; o[nb][3] *= c1;
        }

        if (has_next)
            asm volatile("cp.async.wait_group 1;\n" ::: "memory");   // V[kt]
        else
            asm volatile("cp.async.wait_group 0;\n" ::: "memory");
        __syncthreads();

        // ---- O += P @ V (overlaps in-flight K[kt+1]) ----
        #pragma unroll
        for (int kc = 0; kc < 4; kc++) {          // 4 key-16-groups
            uint2 plo = *(const uint2*)&sP[(w * 16 + g)     * APST + kc * 16 + 4 * l];
            uint2 phi = *(const uint2*)&sP[(w * 16 + g + 8) * APST + kc * 16 + 4 * l];
            unsigned a[4] = {plo.x, phi.x, plo.y, phi.y};
            #pragma unroll
            for (int nb = 0; nb < 16; nb++) {
                uint2 vv = *(const uint2*)&sVt[(nb * 8 + g) * AVST + kc * 16 + 4 * l];
                mma16(o[nb], a, vv.x, vv.y);
            }
        }
        __syncthreads();
        if (has_next) load_v(k0 + 64);
    }

    // ---- epilogue: O /= l, write fp16 k16-interleaved ctx for Wo GEMM ----
    float inv0 = 1.0f / s0, inv1 = 1.0f / s1;
    size_t row0 = (size_t)(b * SS + qrow);
    #pragma unroll
    for (int nb = 0; nb < 16; nb++) {
        size_t cb = h * HD + (nb >> 1) * 16 + 4 * l + 2 * (nb & 1);
        *(__half2*)&Og[row0 * DIM + cb] =
            __floats2half2_rn(o[nb][0] * inv0, o[nb][1] * inv0);
        *(__half2*)&Og[(row0 + 8) * DIM + cb] =
            __floats2half2_rn(o[nb][2] * inv1, o[nb][3] * inv1);
    }
}

// ---------------------------------------------------------------------------
// Launch
// ---------------------------------------------------------------------------
extern "C" void kernel_launch(void* const* d_in, const int* in_sizes, int n_in,
                              void* d_out, int out_size)
{
    const float* X     = (const float*)d_in[0];
    const float* cosT  = (const float*)d_in[1];
    const float* sinT  = (const float*)d_in[2];
    const float* alibi = (const float*)d_in[3];
    const float* amask = (const float*)d_in[4];
    const float* wq    = (const float*)d_in[5];
    const float* wk    = (const float*)d_in[6];
    const float* wv    = (const float*)d_in[7];
    const float* wo    = (const float*)d_in[8];
    float* out = (float*)d_out;

    __half *Xr, *Wt, *Wot, *QKV, *Vt, *C;
    cudaGetSymbolAddress((void**)&Xr,  gXr);
    cudaGetSymbolAddress((void**)&Wt,  gWt);
    cudaGetSymbolAddress((void**)&Wot, gWot);
    cudaGetSymbolAddress((void**)&QKV, gQKV);
    cudaGetSymbolAddress((void**)&Vt,  gVt);
    cudaGetSymbolAddress((void**)&C,   gC);

    cudaFuncSetAttribute(h16_gemm<true>,
                         cudaFuncAttributeMaxDynamicSharedMemorySize, HGEMM_SMEM);
    cudaFuncSetAttribute(h16_gemm<false>,
                         cudaFuncAttributeMaxDynamicSharedMemorySize, HGEMM_SMEM);
    cudaFuncSetAttribute(attn_h,
                         cudaFuncAttributeMaxDynamicSharedMemorySize, ATTN_SMEM);

    // 1: X -> fp16 k16-interleaved
    permute_round_x<<<ROWS * (DIM / 16) / 256, 256>>>(X, Xr);
    // 2: weight packs
    wpack_all<<<dim3(64, 64, 4), dim3(32, 8)>>>(wq, wk, wv, wo, Wt, Wot);
    // 3: fused QKV projection -> fp16
    h16_gemm<true><<<dim3(QKVD / 128, ROWS / 128), 128, HGEMM_SMEM>>>(
        Xr, Wt, QKV, QKVD, DIM);
    // 4,5: RoPE on Q/K (fp16, emits k16-interleaved d)
    rope_h<<<(ROWS * NH * 4 + 255) / 256, 256>>>(QKV, cosT, sinT, 4, QKVD);
    rope_h<<<(ROWS * KVH * 4 + 255) / 256, 256>>>(QKV + KOFF, cosT, sinT, 2, QKVD);
    // 6: V transpose (key-interleaved)
    vtrans<<<dim3(SS / 32, HD / 32, BB * KVH), dim3(32, 8)>>>(QKV, Vt);
    // 7: fp16 flash attention
    attn_h<<<dim3(SS / 64, BB * NH), 128, ATTN_SMEM>>>(QKV, Vt, alibi, amask, C);
    // 8: output projection -> fp32
    h16_gemm<false><<<dim3(DIM / 128, ROWS / 128), 128, HGEMM_SMEM>>>(
        C, Wot, out, DIM, DIM);
}